// round 3
// baseline (speedup 1.0000x reference)
#include <cuda_runtime.h>
#include <math.h>
#include <stdint.h>

#define Bsz   64
#define Lseq  512
#define Edim  10
#define Hdim  1900
#define NOUT  25
#define KT    32
#define NKT   60      // ceil(1900/32)
#define TPB   256

typedef unsigned long long u64;

// ---------------- scratch (__device__ globals; no allocations allowed) ----------------
static __device__ float g_mxT[(size_t)Lseq * Hdim * Bsz];   // [t][j][b]
static __device__ float g_hsT[(size_t)Lseq * Hdim * Bsz];   // [t][j][b]
static __device__ float g_hT[Hdim * Bsz];                   // [j][b]
static __device__ float g_cT[Hdim * Bsz];                   // [j][b]
static __device__ float g_mdot[2][Hdim * Bsz];              // double-buffered h@w_mh.T partials
static __device__ unsigned g_cnt;                           // barrier arrivals (returns to 0)
static __device__ volatile unsigned g_gen;                  // barrier generation

// ---------------- f32x2 helpers ----------------
__device__ __forceinline__ void ffma2(u64 &d, u64 a, u64 b) {
    asm("fma.rn.f32x2 %0, %1, %2, %0;" : "+l"(d) : "l"(a), "l"(b));
}
__device__ __forceinline__ float2 unpack2(u64 v) {
    float2 f; asm("mov.b64 {%0, %1}, %2;" : "=f"(f.x), "=f"(f.y) : "l"(v)); return f;
}

// ---------------- software grid barrier (all blocks co-resident: grid = #SMs) ----------------
__device__ __forceinline__ void gbar() {
    __syncthreads();
    if (threadIdx.x == 0) {
        unsigned gen = g_gen;                 // read BEFORE arriving
        __threadfence();
        if (atomicAdd(&g_cnt, 1u) == gridDim.x - 1) {
            g_cnt = 0;
            __threadfence();
            g_gen = gen + 1;                  // release
        } else {
            while (g_gen == gen) __nanosleep(64);
        }
        __threadfence();                      // acquire
    }
    __syncthreads();
}

// ---------------- 64x64 f32x2 micro-GEMM over one 32-deep K tile ----------------
__device__ __forceinline__ void mma32(u64 acc[4][2],
                                      const float (*w2)[128],
                                      const float (*x)[64],
                                      int rg, int bg) {
#pragma unroll
    for (int kk = 0; kk < KT; kk++) {
        ulonglong2 wa = *(const ulonglong2*)&w2[kk][rg * 8];       // rows rg*4+0,1 (dup pairs)
        ulonglong2 wb = *(const ulonglong2*)&w2[kk][rg * 8 + 4];   // rows rg*4+2,3
        ulonglong2 xv = *(const ulonglong2*)&x[kk][bg * 4];        // b pairs
        ffma2(acc[0][0], wa.x, xv.x); ffma2(acc[0][1], wa.x, xv.y);
        ffma2(acc[1][0], wa.y, xv.x); ffma2(acc[1][1], wa.y, xv.y);
        ffma2(acc[2][0], wb.x, xv.x); ffma2(acc[2][1], wb.x, xv.y);
        ffma2(acc[3][0], wb.y, xv.x); ffma2(acc[3][1], wb.y, xv.y);
    }
}

// ---------------- the whole model in one persistent kernel ----------------
__global__ void __launch_bounds__(TPB, 1) uni_kernel(
    const int*   __restrict__ xb,
    const float* __restrict__ h0,    const float* __restrict__ c0,
    const float* __restrict__ etab,
    const float* __restrict__ w_mx,  const float* __restrict__ w_mh,
    const float* __restrict__ w_ih,  const float* __restrict__ w_hm,
    const float* __restrict__ bias,
    const float* __restrict__ w_lin, const float* __restrict__ b_lin,
    float* __restrict__ out)
{
    __shared__ union SMem {
        struct { float w2[KT][128]; float x[KT][64]; } t;   // 24 KB GEMM tiles
        float g[64][64];                                    // 16 KB gate staging
    } sm;
    __shared__ float s_emb[Bsz][Edim];

    const int tid = threadIdx.x;
    const int rg = tid >> 4, bg = tid & 15;     // 16x16 micro-tile grid (4 rows x 4 b each)
    const int rL = tid & 63, kq = tid >> 6;     // staging roles

    // ================= pre: mxT precompute + state init =================
    for (int unit = blockIdx.x; unit <= Lseq; unit += gridDim.x) {
        if (unit == Lseq) {
            for (int i = tid; i < Hdim * Bsz; i += TPB) {
                int k = i >> 6, b = i & 63;
                g_hT[i] = h0[(size_t)b * Hdim + k];
                g_cT[i] = c0[(size_t)b * Hdim + k];
                g_mdot[0][i] = 0.f;
            }
        } else {
            __syncthreads();
            if (tid < Bsz) {
                int tok = xb[(size_t)tid * Lseq + unit];
#pragma unroll
                for (int e = 0; e < Edim; e++)
                    s_emb[tid][e] = (tok == 0) ? 0.f : etab[(size_t)tok * Edim + e];
            }
            __syncthreads();
            float* outp = g_mxT + (size_t)unit * Hdim * Bsz;
            for (int u = tid; u < Hdim * 4; u += TPB) {
                int r = u >> 2, bq = u & 3;
                float w[Edim];
#pragma unroll
                for (int e = 0; e < Edim; e++) w[e] = w_mx[(size_t)r * Edim + e];
#pragma unroll
                for (int bi = 0; bi < 16; bi++) {
                    int b = bq * 16 + bi;
                    float acc = 0.f;
#pragma unroll
                    for (int e = 0; e < Edim; e++) acc = fmaf(w[e], s_emb[b][e], acc);
                    outp[(size_t)r * 64 + b] = acc;
                }
            }
        }
    }
    gbar();

    // ================= recurrent loop =================
    for (int t = 0; t < Lseq; t++) {
        // ---- phase 1: mdot[j][b] += h[b,:] . w_mh[j,:]  (30 j-tiles x 4 k-splits) ----
        {
            float* dst = g_mdot[t & 1];
            for (int unit = blockIdx.x; unit < 120; unit += gridDim.x) {
                int jt = unit % 30, ks = unit / 30;
                int j0 = jt * 64;
                int jS = j0 + rL;
                bool rowOk = jS < Hdim;
                const float* wrow = w_mh + (size_t)jS * Hdim;
                float xr[8], wr[8];
                u64 acc[4][2] = {};
                int ktb = ks * 15, kte = ktb + 15;
                auto stage = [&](int kt) {
                    int k0 = kt * KT;
#pragma unroll
                    for (int u = 0; u < 8; u++) {
                        int idx = u * TPB + tid;
                        int k = k0 + (idx >> 6);
                        xr[u] = (k < Hdim) ? g_hT[(size_t)k0 * 64 + idx] : 0.f;
                    }
#pragma unroll
                    for (int u = 0; u < 8; u++) {
                        int k = k0 + kq * 8 + u;
                        wr[u] = (rowOk && k < Hdim) ? wrow[k] : 0.f;
                    }
                };
                stage(ktb);
                float* sxf = &sm.t.x[0][0];
                for (int kt = ktb; kt < kte; kt++) {
                    __syncthreads();
#pragma unroll
                    for (int u = 0; u < 8; u++) sxf[u * TPB + tid] = xr[u];
#pragma unroll
                    for (int u = 0; u < 8; u++)
                        *(float2*)&sm.t.w2[kq * 8 + u][2 * rL] = make_float2(wr[u], wr[u]);
                    __syncthreads();
                    if (kt + 1 < kte) stage(kt + 1);
                    mma32(acc, sm.t.w2, sm.t.x, rg, bg);
                }
#pragma unroll
                for (int i = 0; i < 4; i++) {
                    int j = j0 + rg * 4 + i;
                    if (j < Hdim) {
                        float2 a0 = unpack2(acc[i][0]);
                        float2 a1 = unpack2(acc[i][1]);
                        float* p = dst + (size_t)j * 64 + bg * 4;
                        atomicAdd(p + 0, a0.x); atomicAdd(p + 1, a0.y);
                        atomicAdd(p + 2, a1.x); atomicAdd(p + 3, a1.y);
                    }
                }
            }
        }
        gbar();

        // ---- phase 2: gates = (mdot*mx) @ w_hm.T + gx, fused c/h update ----
        {
            // zero next step's mdot buffer (all blocks, grid-stride)
            float* z = g_mdot[(t + 1) & 1];
            for (int i = blockIdx.x * TPB + tid; i < Hdim * Bsz; i += gridDim.x * TPB)
                z[i] = 0.f;

            const float* md = g_mdot[t & 1];
            const float* mx = g_mxT + (size_t)t * Hdim * Bsz;

            for (int unit = blockIdx.x; unit < 119; unit += gridDim.x) {
                int hj0 = unit * 16;
                __syncthreads();
                if (tid < Bsz) {
                    int tok = xb[(size_t)tid * Lseq + t];
#pragma unroll
                    for (int e = 0; e < Edim; e++)
                        s_emb[tid][e] = (tok == 0) ? 0.f : etab[(size_t)tok * Edim + e];
                }
                int gateS = rL >> 4;
                int hjS = hj0 + (rL & 15);
                bool rowOk = hjS < Hdim;
                const float* wrow = w_hm + ((size_t)gateS * Hdim + hjS) * Hdim;
                float xr[8], wr[8];
                u64 acc[4][2] = {};
                auto stage = [&](int kt) {
                    int k0 = kt * KT;
#pragma unroll
                    for (int u = 0; u < 8; u++) {
                        int idx = u * TPB + tid;
                        int k = k0 + (idx >> 6);
                        size_t gi = (size_t)k0 * 64 + idx;
                        xr[u] = (k < Hdim) ? md[gi] * mx[gi] : 0.f;
                    }
#pragma unroll
                    for (int u = 0; u < 8; u++) {
                        int k = k0 + kq * 8 + u;
                        wr[u] = (rowOk && k < Hdim) ? wrow[k] : 0.f;
                    }
                };
                stage(0);
                float* sxf = &sm.t.x[0][0];
                for (int kt = 0; kt < NKT; kt++) {
                    __syncthreads();
#pragma unroll
                    for (int u = 0; u < 8; u++) sxf[u * TPB + tid] = xr[u];
#pragma unroll
                    for (int u = 0; u < 8; u++)
                        *(float2*)&sm.t.w2[kq * 8 + u][2 * rL] = make_float2(wr[u], wr[u]);
                    __syncthreads();
                    if (kt + 1 < NKT) stage(kt + 1);
                    mma32(acc, sm.t.w2, sm.t.x, rg, bg);
                }
                __syncthreads();                 // before aliasing tiles with sm.g
#pragma unroll
                for (int i = 0; i < 4; i++) {
                    float2 a0 = unpack2(acc[i][0]);
                    float2 a1 = unpack2(acc[i][1]);
                    float* gp = &sm.g[rg * 4 + i][bg * 4];
                    gp[0] = a0.x; gp[1] = a0.y; gp[2] = a1.x; gp[3] = a1.y;
                }
                __syncthreads();
                // fused epilogue: gx (K=10) + gates + c/h update
                for (int u = tid; u < 16 * 64; u += TPB) {
                    int hjl = u >> 6, b = u & 63;
                    int hj = hj0 + hjl;
                    if (hj >= Hdim) continue;
                    float gv[4];
#pragma unroll
                    for (int gg = 0; gg < 4; gg++) {
                        int grow = gg * Hdim + hj;
                        float a = bias[grow];
                        const float* wih = w_ih + (size_t)grow * Edim;
#pragma unroll
                        for (int e = 0; e < Edim; e++) a = fmaf(wih[e], s_emb[b][e], a);
                        gv[gg] = a + sm.g[gg * 16 + hjl][b];
                    }
                    size_t idx = (size_t)hj * 64 + b;
                    float c = g_cT[idx];
                    float si = 1.f / (1.f + __expf(-gv[0]));
                    float sf = 1.f / (1.f + __expf(-gv[1]));
                    float so = 1.f / (1.f + __expf(-gv[3]));
                    c = sf * c + si * tanhf(gv[2]);
                    float h = so * tanhf(c);
                    g_cT[idx] = c;
                    g_hT[idx] = h;
                    g_hsT[((size_t)t * Hdim + hj) * 64 + b] = h;
                }
            }
        }
        gbar();
    }

    // ================= final projection: out[b,t,n] = hs . w_lin[n,:] + b_lin ==============
    for (int unit = blockIdx.x; unit < Lseq; unit += gridDim.x) {
        const float* X = g_hsT + (size_t)unit * Hdim * Bsz;
        float accv[7] = {};
        int b = tid & 63, ng = tid >> 6;
        float* sxf = &sm.t.x[0][0];
        for (int kt = 0; kt < NKT; kt++) {
            int k0 = kt * KT;
            __syncthreads();
#pragma unroll
            for (int u = 0; u < 8; u++) {
                int idx = u * TPB + tid;
                int k = k0 + (idx >> 6);
                sxf[idx] = (k < Hdim) ? X[(size_t)k0 * 64 + idx] : 0.f;
            }
            __syncthreads();
            int klim = Hdim - k0; if (klim > KT) klim = KT;
            for (int kk = 0; kk < klim; kk++) {
                float xv = sxf[kk * 64 + b];
#pragma unroll
                for (int q = 0; q < 7; q++) {
                    int n = ng + q * 4;
                    if (n < NOUT) accv[q] = fmaf(xv, w_lin[(size_t)n * Hdim + k0 + kk], accv[q]);
                }
            }
        }
#pragma unroll
        for (int q = 0; q < 7; q++) {
            int n = ng + q * 4;
            if (n < NOUT)
                out[((size_t)b * Lseq + unit) * NOUT + n] = accv[q] + b_lin[n];
        }
    }
}

// ---------------- launcher: ONE graph node ----------------
extern "C" void kernel_launch(void* const* d_in, const int* in_sizes, int n_in,
                              void* d_out, int out_size)
{
    (void)in_sizes; (void)n_in; (void)out_size;
    const int*   xb    = (const int*)  d_in[0];
    // d_in[1] = xb_lens (unused by the reference math)
    const float* h0    = (const float*)d_in[2];
    const float* c0    = (const float*)d_in[3];
    const float* etab  = (const float*)d_in[4];
    const float* w_mx  = (const float*)d_in[5];
    const float* w_mh  = (const float*)d_in[6];
    const float* w_ih  = (const float*)d_in[7];
    const float* w_hm  = (const float*)d_in[8];
    const float* bias  = (const float*)d_in[9];
    const float* w_lin = (const float*)d_in[10];
    const float* b_lin = (const float*)d_in[11];
    float* out = (float*)d_out;

    int sms = 0;
    if (cudaDeviceGetAttribute(&sms, cudaDevAttrMultiProcessorCount, 0) != cudaSuccess || sms <= 0)
        sms = 148;

    uni_kernel<<<sms, TPB>>>(xb, h0, c0, etab, w_mx, w_mh, w_ih, w_hm,
                             bias, w_lin, b_lin, out);
}

// round 4
// speedup vs baseline: 1.3893x; 1.3893x over previous
#include <cuda_runtime.h>
#include <math.h>
#include <stdint.h>

#define Bsz   64
#define Lseq  512
#define Edim  10
#define Hdim  1900
#define Grows 7600   // 4*H
#define NOUT  25
#define KT    32
#define NKT   60      // ceil(1900/32)
#define TPB   256
#define P1KS  18      // P1 k-splits (strided ktiles)
#define P2KS  12      // P2 k-splits (5 contiguous ktiles each)
#define P1RT  8       // P1 rowtiles of 256 (covers 1900)
#define P2RT  30      // P2 rowtiles of 256 (covers 7600)

typedef unsigned long long u64;

// ---------------- scratch (__device__ globals; no allocations allowed) ----------------
static __device__ float g_mxT[(size_t)Lseq * Hdim * Bsz];     // [t][j][b]
static __device__ float g_hsT[(size_t)Lseq * Hdim * Bsz];     // [t][j][b]
static __device__ float g_hT[Hdim * Bsz];                     // [j][b]
static __device__ float g_cT[Hdim * Bsz];                     // [j][b]
static __device__ float g_mdot[2][Hdim * Bsz];                // double-buffered h@w_mh.T partials
static __device__ float g_gpart[P2KS][(size_t)Grows * Bsz];   // per-ksplit gate partials (no atomics)
static __device__ unsigned g_cnt;
static __device__ volatile unsigned g_gen;

// ---------------- f32x2 helpers ----------------
__device__ __forceinline__ void ffma2(u64 &d, u64 a, u64 b) {
    asm("fma.rn.f32x2 %0, %1, %2, %0;" : "+l"(d) : "l"(a), "l"(b));
}
__device__ __forceinline__ u64 dup2(float s) {
    u64 d; asm("mov.b64 %0, {%1, %1};" : "=l"(d) : "f"(s)); return d;
}
__device__ __forceinline__ float2 unpack2(u64 v) {
    float2 f; asm("mov.b64 {%0, %1}, %2;" : "=f"(f.x), "=f"(f.y) : "l"(v)); return f;
}

// ---------------- software grid barrier (grid == #SMs, 1 block/SM) ----------------
__device__ __forceinline__ void gbar() {
    __syncthreads();
    if (threadIdx.x == 0) {
        unsigned gen = g_gen;
        __threadfence();
        if (atomicAdd(&g_cnt, 1u) == gridDim.x - 1) {
            g_cnt = 0;
            __threadfence();
            g_gen = gen + 1;
        } else {
            while (g_gen == gen) __nanosleep(32);
        }
        __threadfence();
    }
    __syncthreads();
}

// ---------------- 256x64 tile: 8 rows x 8 b per thread, f32x2 math ----------------
// sw: [KT][256] natural weights (w[k][row]); sx: [KT][64] natural x (x[k][b])
__device__ __forceinline__ void mma256(u64 acc[8][4],
                                       const float (*__restrict__ sw)[256],
                                       const float (*__restrict__ sx)[64],
                                       int rq, int bq) {
#pragma unroll
    for (int kk = 0; kk < KT; kk++) {
        float4 wv0 = *(const float4*)&sw[kk][rq * 8];
        float4 wv1 = *(const float4*)&sw[kk][rq * 8 + 4];
        ulonglong2 xa = *(const ulonglong2*)&sx[kk][bq * 8];
        ulonglong2 xb = *(const ulonglong2*)&sx[kk][bq * 8 + 4];
        u64 w[8];
        w[0] = dup2(wv0.x); w[1] = dup2(wv0.y); w[2] = dup2(wv0.z); w[3] = dup2(wv0.w);
        w[4] = dup2(wv1.x); w[5] = dup2(wv1.y); w[6] = dup2(wv1.z); w[7] = dup2(wv1.w);
#pragma unroll
        for (int r = 0; r < 8; r++) {
            ffma2(acc[r][0], w[r], xa.x);
            ffma2(acc[r][1], w[r], xa.y);
            ffma2(acc[r][2], w[r], xb.x);
            ffma2(acc[r][3], w[r], xb.y);
        }
    }
}

// ---------------- the whole model in one persistent kernel ----------------
__global__ void __launch_bounds__(TPB, 1) uni_kernel(
    const int*   __restrict__ xb,
    const float* __restrict__ h0,    const float* __restrict__ c0,
    const float* __restrict__ etab,
    const float* __restrict__ w_mx,  const float* __restrict__ w_mh,
    const float* __restrict__ w_ih,  const float* __restrict__ w_hm,
    const float* __restrict__ bias,
    const float* __restrict__ w_lin, const float* __restrict__ b_lin,
    float* __restrict__ out)
{
    __shared__ __align__(16) float s_w[KT][256];   // 32 KB
    __shared__ __align__(16) float s_x[KT][64];    // 8 KB
    __shared__ float s_emb[Bsz][Edim];             // 2.5 KB

    const int tid = threadIdx.x;
    const int rq = tid >> 3, bq = tid & 7;         // 32 rowgroups x 8 bgroups (8x8 per thread)

    // ================= pre: state init + mxT precompute =================
    for (int i = blockIdx.x * TPB + tid; i < Hdim * Bsz; i += gridDim.x * TPB) {
        int k = i >> 6, b = i & 63;
        g_hT[i] = h0[(size_t)b * Hdim + k];
        g_cT[i] = c0[(size_t)b * Hdim + k];
        g_mdot[0][i] = 0.f;
    }
    for (int unit = blockIdx.x; unit < Lseq; unit += gridDim.x) {
        __syncthreads();
        if (tid < Bsz) {
            int tok = xb[(size_t)tid * Lseq + unit];
#pragma unroll
            for (int e = 0; e < Edim; e++)
                s_emb[tid][e] = (tok == 0) ? 0.f : etab[(size_t)tok * Edim + e];
        }
        __syncthreads();
        float* outp = g_mxT + (size_t)unit * Hdim * Bsz;
        for (int u = tid; u < Hdim * 4; u += TPB) {
            int r = u >> 2, bq4 = u & 3;
            float w[Edim];
#pragma unroll
            for (int e = 0; e < Edim; e++) w[e] = w_mx[(size_t)r * Edim + e];
#pragma unroll
            for (int bi = 0; bi < 16; bi++) {
                int b = bq4 * 16 + bi;
                float acc = 0.f;
#pragma unroll
                for (int e = 0; e < Edim; e++) acc = fmaf(w[e], s_emb[b][e], acc);
                outp[(size_t)r * 64 + b] = acc;
            }
        }
    }
    gbar();

    // ================= recurrent loop =================
    for (int t = 0; t < Lseq; t++) {
        // ---- P1: mdot[j][b] += h . w_mh[j,:]  (8 rowtiles x 18 strided k-splits) ----
        {
            float* dst = g_mdot[t & 1];
            for (int unit = blockIdx.x; unit < P1RT * P1KS; unit += gridDim.x) {
                int rt = unit / P1KS, ks = unit % P1KS;
                int row0 = rt * 256;
                int rS = row0 + tid;
                bool rowOk = rS < Hdim;
                const float* wrow = w_mh + (size_t)rS * Hdim;
                float wr[KT], xr[8];
                u64 acc[8][4] = {};
                auto stage = [&](int kt) {
                    int k0 = kt * KT;
#pragma unroll
                    for (int u = 0; u < KT; u++) {
                        int k = k0 + u;
                        wr[u] = (rowOk && k < Hdim) ? wrow[k] : 0.f;
                    }
#pragma unroll
                    for (int u = 0; u < 8; u++) {
                        int idx = u * TPB + tid;
                        int k = k0 + (idx >> 6);
                        xr[u] = (k < Hdim) ? g_hT[(size_t)k0 * 64 + idx] : 0.f;
                    }
                };
                stage(ks);
                for (int kt = ks; kt < NKT; kt += P1KS) {
                    __syncthreads();
#pragma unroll
                    for (int u = 0; u < KT; u++) s_w[u][tid] = wr[u];
#pragma unroll
                    for (int u = 0; u < 8; u++) (&s_x[0][0])[u * TPB + tid] = xr[u];
                    __syncthreads();
                    if (kt + P1KS < NKT) stage(kt + P1KS);
                    mma256(acc, s_w, s_x, rq, bq);
                }
#pragma unroll
                for (int r = 0; r < 8; r++) {
                    int j = row0 + rq * 8 + r;
                    if (j < Hdim) {
                        float* p = dst + (size_t)j * 64 + bq * 8;
#pragma unroll
                        for (int pp = 0; pp < 4; pp++) {
                            float2 v = unpack2(acc[r][pp]);
                            atomicAdd(p + 2 * pp, v.x);
                            atomicAdd(p + 2 * pp + 1, v.y);
                        }
                    }
                }
            }
        }
        gbar();

        // ---- P2: gate partials = w_hm . (mdot*mx)  (30 rowtiles x 12 k-splits) ----
        {
            const float* md = g_mdot[t & 1];
            const float* mx = g_mxT + (size_t)t * Hdim * Bsz;
            for (int unit = blockIdx.x; unit < P2RT * P2KS; unit += gridDim.x) {
                int rt = unit / P2KS, ks = unit % P2KS;
                int row0 = rt * 256;
                int rS = row0 + tid;
                bool rowOk = rS < Grows;
                const float* wrow = w_hm + (size_t)rS * Hdim;
                float wr[KT], xr[8];
                u64 acc[8][4] = {};
                auto stage = [&](int kt) {
                    int k0 = kt * KT;
#pragma unroll
                    for (int u = 0; u < KT; u++) {
                        int k = k0 + u;
                        wr[u] = (rowOk && k < Hdim) ? wrow[k] : 0.f;
                    }
#pragma unroll
                    for (int u = 0; u < 8; u++) {
                        int idx = u * TPB + tid;
                        int k = k0 + (idx >> 6);
                        size_t gi = (size_t)k0 * 64 + idx;
                        xr[u] = (k < Hdim) ? md[gi] * mx[gi] : 0.f;
                    }
                };
                int ktb = ks * 5, kte = ktb + 5;
                stage(ktb);
                for (int kt = ktb; kt < kte; kt++) {
                    __syncthreads();
#pragma unroll
                    for (int u = 0; u < KT; u++) s_w[u][tid] = wr[u];
#pragma unroll
                    for (int u = 0; u < 8; u++) (&s_x[0][0])[u * TPB + tid] = xr[u];
                    __syncthreads();
                    if (kt + 1 < kte) stage(kt + 1);
                    mma256(acc, s_w, s_x, rq, bq);
                }
                float* gp = g_gpart[ks];
#pragma unroll
                for (int r = 0; r < 8; r++) {
                    int row = row0 + rq * 8 + r;
                    if (row < Grows) {
                        u64* p = (u64*)(gp + (size_t)row * 64 + bq * 8);
                        *(ulonglong2*)(p)     = make_ulonglong2(acc[r][0], acc[r][1]);
                        *(ulonglong2*)(p + 2) = make_ulonglong2(acc[r][2], acc[r][3]);
                    }
                }
            }
        }
        gbar();

        // ---- P3: epilogue — sum partials + gx(K=10) + c/h update; zero next mdot ----
        {
            __syncthreads();
            if (tid < Bsz) {
                int tok = xb[(size_t)tid * Lseq + t];
#pragma unroll
                for (int e = 0; e < Edim; e++)
                    s_emb[tid][e] = (tok == 0) ? 0.f : etab[(size_t)tok * Edim + e];
            }
            __syncthreads();
            for (int u = blockIdx.x * TPB + tid; u < Hdim * Bsz; u += gridDim.x * TPB) {
                int hj = u >> 6, b = u & 63;
                float gv[4];
#pragma unroll
                for (int gg = 0; gg < 4; gg++) {
                    int r = gg * Hdim + hj;
                    float a = bias[r];
                    const float* wih = w_ih + (size_t)r * Edim;
#pragma unroll
                    for (int e = 0; e < Edim; e++) a = fmaf(wih[e], s_emb[b][e], a);
#pragma unroll
                    for (int ks = 0; ks < P2KS; ks++)
                        a += g_gpart[ks][(size_t)r * 64 + b];
                    gv[gg] = a;
                }
                float c = g_cT[u];
                float si = __fdividef(1.f, 1.f + __expf(-gv[0]));
                float sf = __fdividef(1.f, 1.f + __expf(-gv[1]));
                float so = __fdividef(1.f, 1.f + __expf(-gv[3]));
                c = sf * c + si * tanhf(gv[2]);
                float h = so * tanhf(c);
                g_cT[u] = c;
                g_hT[u] = h;
                g_hsT[(size_t)t * Hdim * Bsz + u] = h;
            }
            float* z = g_mdot[(t + 1) & 1];
            for (int i = blockIdx.x * TPB + tid; i < Hdim * Bsz; i += gridDim.x * TPB)
                z[i] = 0.f;
        }
        gbar();
    }

    // ================= final projection: out[b,t,n] = hs . w_lin[n,:] + b_lin ==============
    for (int unit = blockIdx.x; unit < Lseq; unit += gridDim.x) {
        const float* X = g_hsT + (size_t)unit * Hdim * Bsz;
        float accv[7] = {};
        int b = tid & 63, ng = tid >> 6;
        float* sxf = &s_x[0][0];
        for (int kt = 0; kt < NKT; kt++) {
            int k0 = kt * KT;
            __syncthreads();
#pragma unroll
            for (int u = 0; u < 8; u++) {
                int idx = u * TPB + tid;
                int k = k0 + (idx >> 6);
                sxf[idx] = (k < Hdim) ? X[(size_t)k0 * 64 + idx] : 0.f;
            }
            __syncthreads();
            int klim = Hdim - k0; if (klim > KT) klim = KT;
            for (int kk = 0; kk < klim; kk++) {
                float xv = sxf[kk * 64 + b];
#pragma unroll
                for (int q = 0; q < 7; q++) {
                    int n = ng + q * 4;
                    if (n < NOUT) accv[q] = fmaf(xv, w_lin[(size_t)n * Hdim + k0 + kk], accv[q]);
                }
            }
        }
#pragma unroll
        for (int q = 0; q < 7; q++) {
            int n = ng + q * 4;
            if (n < NOUT)
                out[((size_t)b * Lseq + unit) * NOUT + n] = accv[q] + b_lin[n];
        }
    }
}

// ---------------- launcher: ONE graph node ----------------
extern "C" void kernel_launch(void* const* d_in, const int* in_sizes, int n_in,
                              void* d_out, int out_size)
{
    (void)in_sizes; (void)n_in; (void)out_size;
    const int*   xb    = (const int*)  d_in[0];
    // d_in[1] = xb_lens (unused by the reference math)
    const float* h0    = (const float*)d_in[2];
    const float* c0    = (const float*)d_in[3];
    const float* etab  = (const float*)d_in[4];
    const float* w_mx  = (const float*)d_in[5];
    const float* w_mh  = (const float*)d_in[6];
    const float* w_ih  = (const float*)d_in[7];
    const float* w_hm  = (const float*)d_in[8];
    const float* bias  = (const float*)d_in[9];
    const float* w_lin = (const float*)d_in[10];
    const float* b_lin = (const float*)d_in[11];
    float* out = (float*)d_out;

    int sms = 0;
    if (cudaDeviceGetAttribute(&sms, cudaDevAttrMultiProcessorCount, 0) != cudaSuccess || sms <= 0)
        sms = 148;

    uni_kernel<<<sms, TPB>>>(xb, h0, c0, etab, w_mx, w_mh, w_ih, w_hm,
                             bias, w_lin, b_lin, out);
}

// round 6
// speedup vs baseline: 1.6766x; 1.2068x over previous
#include <cuda_runtime.h>
#include <math.h>
#include <stdint.h>

#define Bsz   64
#define Lseq  512
#define Edim  10
#define Hdim  1900
#define Grows 7600      // 4*H
#define NOUT  25
#define KT    32
#define NKT   60        // ceil(1900/32)
#define TPB   512
#define NTOK  30
#define P1KS  18
#define P2KS  12
#define HB    (Hdim * Bsz)   // 121600
#define SMEM_BYTES ((KT * 256 + KT * 128) * 4)   // 49152

typedef unsigned long long u64;

// ---------------- scratch (__device__ globals; no allocations allowed) ----------------
static __device__ float g_mxT[(size_t)Lseq * HB];            // [t][j][b]
static __device__ float g_hsT[(size_t)Lseq * HB];            // [t][j][b]
static __device__ float g_hT[HB];                            // [j][b]
static __device__ float g_cT[HB];                            // [j][b]
static __device__ float g_mdot[2][HB];                       // double-buffered h@w_mh.T
static __device__ float g_gpart[P2KS][(size_t)Grows * Bsz];  // P2 k-split partials
static __device__ float g_mxtok[NTOK][Hdim];                 // per-token mx row
static __device__ float g_gxtok[NTOK][Grows];                // per-token gate-input row (incl bias)
static __device__ unsigned g_cnt;
static __device__ volatile unsigned g_gen;

// ---------------- f32x2 helpers ----------------
__device__ __forceinline__ void ffma2(u64 &d, u64 a, u64 b) {
    asm("fma.rn.f32x2 %0, %1, %2, %0;" : "+l"(d) : "l"(a), "l"(b));
}
__device__ __forceinline__ float2 unpack2(u64 v) {
    float2 f; asm("mov.b64 {%0, %1}, %2;" : "=f"(f.x), "=f"(f.y) : "l"(v)); return f;
}

// ---------------- software grid barrier (grid == #SMs, 1 block/SM) ----------------
__device__ __forceinline__ void gbar() {
    __syncthreads();
    if (threadIdx.x == 0) {
        unsigned gen = g_gen;
        __threadfence();
        if (atomicAdd(&g_cnt, 1u) == gridDim.x - 1) {
            g_cnt = 0;
            __threadfence();
            g_gen = gen + 1;
        } else {
            while (g_gen == gen) __nanosleep(32);
        }
        __threadfence();
    }
    __syncthreads();
}

// ---------------- 256row x 64b tile mma: rows packed in pairs, x pre-duplicated ----------------
// sw: swizzled transposed W [k][256]; sx2: [k][128] (b duplicated)
__device__ __forceinline__ void mma_unit(u64 acc[4][4],
                                         const float* __restrict__ sw,
                                         const float* __restrict__ sx2,
                                         int rq, int bq) {
#pragma unroll
    for (int kk = 0; kk < KT; kk++) {
        const int Ck = (kk & 7) ^ ((kk >> 3) & 3);
        float4 wa = *(const float4*)(sw + kk * 256 + (((2 * rq)     ^ Ck) << 2)); // rows 8rq..8rq+3
        float4 wb = *(const float4*)(sw + kk * 256 + (((2 * rq + 1) ^ Ck) << 2)); // rows 8rq+4..+7
        ulonglong2 x0 = *(const ulonglong2*)(sx2 + kk * 128 + bq * 8);     // dup(b0), dup(b1)
        ulonglong2 x1 = *(const ulonglong2*)(sx2 + kk * 128 + bq * 8 + 4); // dup(b2), dup(b3)
        u64 wp0 = ((const u64*)&wa)[0], wp1 = ((const u64*)&wa)[1];
        u64 wp2 = ((const u64*)&wb)[0], wp3 = ((const u64*)&wb)[1];
        ffma2(acc[0][0], wp0, x0.x); ffma2(acc[0][1], wp0, x0.y); ffma2(acc[0][2], wp0, x1.x); ffma2(acc[0][3], wp0, x1.y);
        ffma2(acc[1][0], wp1, x0.x); ffma2(acc[1][1], wp1, x0.y); ffma2(acc[1][2], wp1, x1.x); ffma2(acc[1][3], wp1, x1.y);
        ffma2(acc[2][0], wp2, x0.x); ffma2(acc[2][1], wp2, x0.y); ffma2(acc[2][2], wp2, x1.x); ffma2(acc[2][3], wp2, x1.y);
        ffma2(acc[3][0], wp3, x0.x); ffma2(acc[3][1], wp3, x0.y); ffma2(acc[3][2], wp3, x1.x); ffma2(acc[3][3], wp3, x1.y);
    }
}

// ---------------- persistent kernel ----------------
__global__ void __launch_bounds__(TPB, 1) uni_kernel(
    const int*   __restrict__ xb,
    const float* __restrict__ h0,    const float* __restrict__ c0,
    const float* __restrict__ etab,
    const float* __restrict__ w_mx,  const float* __restrict__ w_mh,
    const float* __restrict__ w_ih,  const float* __restrict__ w_hm,
    const float* __restrict__ bias,
    const float* __restrict__ w_lin, const float* __restrict__ b_lin,
    float* __restrict__ out)
{
    extern __shared__ __align__(16) float smem[];
    float* s_w  = smem;               // KT*256 floats, swizzled transposed W
    float* s_x2 = smem + KT * 256;    // KT*128 floats, x duplicated pairs
    __shared__ int s_tok[Bsz];

    const int tid = threadIdx.x;
    // GEMM thread mapping: rq in 0..31 (8 consecutive rows each), bq in 0..15 (4 b each)
    const int rq = (tid & 3) | (((tid >> 5) & 7) << 2);
    const int bq = ((tid >> 2) & 7) | ((tid >> 8) << 3);

    // ================= pre: token tables + state init + mxT =================
    for (int i = blockIdx.x * TPB + tid; i < NTOK * Hdim; i += gridDim.x * TPB) {
        int v = i / Hdim, j = i - v * Hdim;
        float a = 0.f;
        if (v != 0) {
#pragma unroll
            for (int e = 0; e < Edim; e++)
                a = fmaf(etab[(size_t)v * Edim + e], w_mx[(size_t)j * Edim + e], a);
        }
        g_mxtok[v][j] = a;
    }
    for (int i = blockIdx.x * TPB + tid; i < NTOK * Grows; i += gridDim.x * TPB) {
        int v = i / Grows, r = i - v * Grows;
        float a = bias[r];
        if (v != 0) {
#pragma unroll
            for (int e = 0; e < Edim; e++)
                a = fmaf(etab[(size_t)v * Edim + e], w_ih[(size_t)r * Edim + e], a);
        }
        g_gxtok[v][r] = a;
    }
    for (int i = blockIdx.x * TPB + tid; i < HB; i += gridDim.x * TPB) {
        int k = i >> 6, b = i & 63;
        g_hT[i] = h0[(size_t)b * Hdim + k];
        g_cT[i] = c0[(size_t)b * Hdim + k];
        g_mdot[0][i] = 0.f;
    }
    gbar();
    // materialize mxT via token gather
    for (int unit = blockIdx.x; unit < Lseq; unit += gridDim.x) {
        __syncthreads();
        if (tid < Bsz) s_tok[tid] = xb[(size_t)tid * Lseq + unit];
        __syncthreads();
        float* dst = g_mxT + (size_t)unit * HB;
        for (int i = tid; i < HB; i += TPB) {
            int j = i >> 6, b = i & 63;
            dst[i] = g_mxtok[s_tok[b]][j];
        }
    }
    gbar();

    // ================= recurrent loop =================
    for (int t = 0; t < Lseq; t++) {
        // ---- P1: mdot = h @ w_mh.T (8 rowtiles x 18 k-splits, atomic accumulate) ----
        {
            float* dst = g_mdot[t & 1];
            for (int unit = blockIdx.x; unit < 8 * P1KS; unit += gridDim.x) {
                int rt = unit / P1KS, ks = unit - rt * P1KS;
                int row0 = rt * 256;
                int ktb = (ks * NKT) / P1KS, kte = ((ks + 1) * NKT) / P1KS;
                u64 acc[4][4] = {};
                float4 wv[4];
                float  xv[4];
                auto stage = [&](int kt) {
                    int k0 = kt * KT;
#pragma unroll
                    for (int u = 0; u < 4; u++) {
                        int f4 = u * TPB + tid;
                        int row = f4 >> 3, kq4 = f4 & 7;
                        int gr = row0 + row, gk = k0 + kq4 * 4;
                        float4 v = make_float4(0.f, 0.f, 0.f, 0.f);
                        if (gr < Hdim) {
                            if (gk + 3 < Hdim) v = *(const float4*)(w_mh + (size_t)gr * Hdim + gk);
                            else {
                                float* pv = (float*)&v;
#pragma unroll
                                for (int j = 0; j < 4; j++)
                                    if (gk + j < Hdim) pv[j] = w_mh[(size_t)gr * Hdim + gk + j];
                            }
                        }
                        wv[u] = v;
                    }
#pragma unroll
                    for (int u = 0; u < 4; u++) {
                        int idx = u * TPB + tid;
                        int k = k0 + (idx >> 6);
                        xv[u] = (k < Hdim) ? g_hT[(size_t)k0 * 64 + idx] : 0.f;
                    }
                };
                stage(ktb);
                for (int kt = ktb; kt < kte; kt++) {
                    __syncthreads();
#pragma unroll
                    for (int u = 0; u < 4; u++) {
                        int f4 = u * TPB + tid;
                        int row = f4 >> 3, kq4 = f4 & 7;
                        const float* pv = (const float*)&wv[u];
#pragma unroll
                        for (int j = 0; j < 4; j++) {
                            int k = kq4 * 4 + j;
                            int col4 = (row >> 2) ^ (k & 7) ^ ((k >> 3) & 3);
                            s_w[k * 256 + col4 * 4 + (row & 3)] = pv[j];
                        }
                    }
#pragma unroll
                    for (int u = 0; u < 4; u++) {
                        int idx = u * TPB + tid;
                        float v = xv[u];
                        *(float2*)(s_x2 + 2 * idx) = make_float2(v, v);
                    }
                    __syncthreads();
                    if (kt + 1 < kte) stage(kt + 1);
                    mma_unit(acc, s_w, s_x2, rq, bq);
                }
#pragma unroll
                for (int rp = 0; rp < 4; rp++) {
                    int r0 = row0 + rq * 8 + rp * 2;
#pragma unroll
                    for (int bb = 0; bb < 4; bb++) {
                        float2 v = unpack2(acc[rp][bb]);
                        int b = bq * 4 + bb;
                        if (r0 < Hdim)     atomicAdd(&dst[(size_t)r0 * 64 + b], v.x);
                        if (r0 + 1 < Hdim) atomicAdd(&dst[(size_t)(r0 + 1) * 64 + b], v.y);
                    }
                }
            }
        }
        gbar();

        // ---- P2: gate partials = w_hm @ (mdot*mx)  (30 rowtiles x 12 k-splits) ----
        {
            const float* md = g_mdot[t & 1];
            const float* mx = g_mxT + (size_t)t * HB;
            for (int unit = blockIdx.x; unit < 30 * P2KS; unit += gridDim.x) {
                int rt = unit / P2KS, ks = unit - rt * P2KS;
                int row0 = rt * 256;
                int ktb = ks * 5, kte = ktb + 5;
                u64 acc[4][4] = {};
                float4 wv[4];
                float  xv[4];
                auto stage = [&](int kt) {
                    int k0 = kt * KT;
#pragma unroll
                    for (int u = 0; u < 4; u++) {
                        int f4 = u * TPB + tid;
                        int row = f4 >> 3, kq4 = f4 & 7;
                        int gr = row0 + row, gk = k0 + kq4 * 4;
                        float4 v = make_float4(0.f, 0.f, 0.f, 0.f);
                        if (gr < Grows) {
                            if (gk + 3 < Hdim) v = *(const float4*)(w_hm + (size_t)gr * Hdim + gk);
                            else {
                                float* pv = (float*)&v;
#pragma unroll
                                for (int j = 0; j < 4; j++)
                                    if (gk + j < Hdim) pv[j] = w_hm[(size_t)gr * Hdim + gk + j];
                            }
                        }
                        wv[u] = v;
                    }
#pragma unroll
                    for (int u = 0; u < 4; u++) {
                        int idx = u * TPB + tid;
                        int k = k0 + (idx >> 6);
                        size_t gi = (size_t)k0 * 64 + idx;
                        xv[u] = (k < Hdim) ? md[gi] * mx[gi] : 0.f;
                    }
                };
                stage(ktb);
                for (int kt = ktb; kt < kte; kt++) {
                    __syncthreads();
#pragma unroll
                    for (int u = 0; u < 4; u++) {
                        int f4 = u * TPB + tid;
                        int row = f4 >> 3, kq4 = f4 & 7;
                        const float* pv = (const float*)&wv[u];
#pragma unroll
                        for (int j = 0; j < 4; j++) {
                            int k = kq4 * 4 + j;
                            int col4 = (row >> 2) ^ (k & 7) ^ ((k >> 3) & 3);
                            s_w[k * 256 + col4 * 4 + (row & 3)] = pv[j];
                        }
                    }
#pragma unroll
                    for (int u = 0; u < 4; u++) {
                        int idx = u * TPB + tid;
                        float v = xv[u];
                        *(float2*)(s_x2 + 2 * idx) = make_float2(v, v);
                    }
                    __syncthreads();
                    if (kt + 1 < kte) stage(kt + 1);
                    mma_unit(acc, s_w, s_x2, rq, bq);
                }
                float* gp = g_gpart[ks];
#pragma unroll
                for (int rp = 0; rp < 4; rp++) {
                    float2 v0 = unpack2(acc[rp][0]);
                    float2 v1 = unpack2(acc[rp][1]);
                    float2 v2 = unpack2(acc[rp][2]);
                    float2 v3 = unpack2(acc[rp][3]);
                    int r0 = row0 + rq * 8 + rp * 2;
                    if (r0 < Grows)
                        *(float4*)(gp + (size_t)r0 * 64 + bq * 4) = make_float4(v0.x, v1.x, v2.x, v3.x);
                    if (r0 + 1 < Grows)
                        *(float4*)(gp + (size_t)(r0 + 1) * 64 + bq * 4) = make_float4(v0.y, v1.y, v2.y, v3.y);
                }
            }
        }
        gbar();

        // ---- P3: epilogue — sum partials + gxtok + c/h update; zero next mdot ----
        {
            if (tid < Bsz) s_tok[tid] = xb[(size_t)tid * Lseq + t];
            __syncthreads();
            for (int u = blockIdx.x * TPB + tid; u < HB; u += gridDim.x * TPB) {
                int hj = u >> 6, b = u & 63;
                int tok = s_tok[b];
                float gv[4];
#pragma unroll
                for (int gg = 0; gg < 4; gg++) {
                    int r = gg * Hdim + hj;
                    float a = g_gxtok[tok][r];
#pragma unroll
                    for (int ks = 0; ks < P2KS; ks++)
                        a += g_gpart[ks][(size_t)r * 64 + b];
                    gv[gg] = a;
                }
                float c = g_cT[u];
                float si = __fdividef(1.f, 1.f + __expf(-gv[0]));
                float sf = __fdividef(1.f, 1.f + __expf(-gv[1]));
                float so = __fdividef(1.f, 1.f + __expf(-gv[3]));
                c = sf * c + si * tanhf(gv[2]);
                float h = so * tanhf(c);
                g_cT[u] = c;
                g_hT[u] = h;
                g_hsT[(size_t)t * HB + u] = h;
            }
            float* z = g_mdot[(t + 1) & 1];
            for (int i = blockIdx.x * TPB + tid; i < HB; i += gridDim.x * TPB)
                z[i] = 0.f;
        }
        gbar();
    }

    // ================= final projection: out[b,t,n] = hs . w_lin[n,:] + b_lin ==============
    for (int unit = blockIdx.x; unit < Lseq; unit += gridDim.x) {
        const float* X = g_hsT + (size_t)unit * HB;
        float accv[4] = {};
        int b = tid & 63, ng = tid >> 6;   // ng 0..7
        for (int kt = 0; kt < NKT; kt++) {
            int k0 = kt * KT;
            __syncthreads();
#pragma unroll
            for (int u = 0; u < 4; u++) {
                int idx = u * TPB + tid;
                int k = k0 + (idx >> 6);
                s_x2[idx] = (k < Hdim) ? X[(size_t)k0 * 64 + idx] : 0.f;
            }
            __syncthreads();
            int klim = Hdim - k0; if (klim > KT) klim = KT;
            for (int kk = 0; kk < klim; kk++) {
                float xv = s_x2[kk * 64 + b];
#pragma unroll
                for (int q = 0; q < 4; q++) {
                    int n = ng + q * 8;
                    if (n < NOUT) accv[q] = fmaf(xv, w_lin[(size_t)n * Hdim + k0 + kk], accv[q]);
                }
            }
        }
#pragma unroll
        for (int q = 0; q < 4; q++) {
            int n = ng + q * 8;
            if (n < NOUT)
                out[((size_t)b * Lseq + unit) * NOUT + n] = accv[q] + b_lin[n];
        }
    }
}

// ---------------- launcher: ONE graph node ----------------
extern "C" void kernel_launch(void* const* d_in, const int* in_sizes, int n_in,
                              void* d_out, int out_size)
{
    (void)in_sizes; (void)n_in; (void)out_size;
    const int*   xb    = (const int*)  d_in[0];
    // d_in[1] = xb_lens (unused by the reference math)
    const float* h0    = (const float*)d_in[2];
    const float* c0    = (const float*)d_in[3];
    const float* etab  = (const float*)d_in[4];
    const float* w_mx  = (const float*)d_in[5];
    const float* w_mh  = (const float*)d_in[6];
    const float* w_ih  = (const float*)d_in[7];
    const float* w_hm  = (const float*)d_in[8];
    const float* bias  = (const float*)d_in[9];
    const float* w_lin = (const float*)d_in[10];
    const float* b_lin = (const float*)d_in[11];
    float* out = (float*)d_out;

    static int smem_set = 0;
    if (!smem_set) {
        cudaFuncSetAttribute(uni_kernel, cudaFuncAttributeMaxDynamicSharedMemorySize, SMEM_BYTES);
        smem_set = 1;
    }

    int sms = 0;
    if (cudaDeviceGetAttribute(&sms, cudaDevAttrMultiProcessorCount, 0) != cudaSuccess || sms <= 0)
        sms = 148;

    uni_kernel<<<sms, TPB, SMEM_BYTES>>>(xb, h0, c0, etab, w_mx, w_mh, w_ih, w_hm,
                                         bias, w_lin, b_lin, out);
}

// round 7
// speedup vs baseline: 1.7670x; 1.0539x over previous
#include <cuda_runtime.h>
#include <math.h>
#include <stdint.h>

#define Bsz   64
#define Lseq  512
#define Edim  10
#define Hdim  1900
#define Grows 7600      // 4*H
#define NOUT  25
#define KT    32
#define NKT   60        // ceil(1900/32)
#define TPB   512
#define NTOK  30
#define P1KS  18
#define P2KS  12
#define NU1   (8 * P1KS)     // 144 P1 units
#define NU2   (30 * P2KS)    // 360 P2 units
#define HB    (Hdim * Bsz)   // 121600
#define BUFSTRIDE (KT * 384)                    // floats per smem buffer (W + X2)
#define SMEM_BYTES (2 * BUFSTRIDE * 4)          // 98304

typedef unsigned long long u64;

// ---------------- scratch (__device__ globals; no allocations allowed) ----------------
static __device__ float g_mxT[(size_t)Lseq * HB];            // [t][j][b]
static __device__ float g_hsT[(size_t)Lseq * HB];            // [t][j][b]
static __device__ float g_hT[HB];                            // [j][b]
static __device__ float g_cT[HB];                            // [j][b]
static __device__ float g_x2T[HB];                           // mdot*mx (built in P1.5)
static __device__ float g_m1part[P1KS][HB];                  // P1 k-split partials
static __device__ float g_gpart[P2KS][(size_t)Grows * Bsz];  // P2 k-split partials
static __device__ float g_mxtok[NTOK][Hdim];                 // per-token mx row
static __device__ float g_gxtok[NTOK][Grows];                // per-token gate input (incl bias)
static __device__ unsigned g_tkt1, g_tkt2;                   // phase tickets
static __device__ unsigned g_cnt;
static __device__ volatile unsigned g_gen;

// ---------------- f32x2 helpers ----------------
__device__ __forceinline__ void ffma2(u64 &d, u64 a, u64 b) {
    asm("fma.rn.f32x2 %0, %1, %2, %0;" : "+l"(d) : "l"(a), "l"(b));
}
__device__ __forceinline__ float2 unpack2(u64 v) {
    float2 f; asm("mov.b64 {%0, %1}, %2;" : "=f"(f.x), "=f"(f.y) : "l"(v)); return f;
}

// ---------------- software grid barrier (grid == #SMs, 1 block/SM) ----------------
__device__ __forceinline__ void gbar() {
    __syncthreads();
    if (threadIdx.x == 0) {
        unsigned gen = g_gen;
        __threadfence();
        if (atomicAdd(&g_cnt, 1u) == gridDim.x - 1) {
            g_cnt = 0;
            __threadfence();
            g_gen = gen + 1;
        } else {
            while (g_gen == gen) __nanosleep(32);
        }
        __threadfence();
    }
    __syncthreads();
}

// ---------------- 256row x 64b tile mma: row pairs packed, x pre-duplicated ----------------
__device__ __forceinline__ void mma_unit(u64 acc[4][4],
                                         const float* __restrict__ sw,
                                         const float* __restrict__ sx2,
                                         int rq, int bq) {
#pragma unroll
    for (int kk = 0; kk < KT; kk++) {
        const int Ck = (kk & 7) ^ ((kk >> 3) & 3);
        float4 wa = *(const float4*)(sw + kk * 256 + (((2 * rq)     ^ Ck) << 2));
        float4 wb = *(const float4*)(sw + kk * 256 + (((2 * rq + 1) ^ Ck) << 2));
        ulonglong2 x0 = *(const ulonglong2*)(sx2 + kk * 128 + bq * 8);
        ulonglong2 x1 = *(const ulonglong2*)(sx2 + kk * 128 + bq * 8 + 4);
        u64 wp0 = ((const u64*)&wa)[0], wp1 = ((const u64*)&wa)[1];
        u64 wp2 = ((const u64*)&wb)[0], wp3 = ((const u64*)&wb)[1];
        ffma2(acc[0][0], wp0, x0.x); ffma2(acc[0][1], wp0, x0.y); ffma2(acc[0][2], wp0, x1.x); ffma2(acc[0][3], wp0, x1.y);
        ffma2(acc[1][0], wp1, x0.x); ffma2(acc[1][1], wp1, x0.y); ffma2(acc[1][2], wp1, x1.x); ffma2(acc[1][3], wp1, x1.y);
        ffma2(acc[2][0], wp2, x0.x); ffma2(acc[2][1], wp2, x0.y); ffma2(acc[2][2], wp2, x1.x); ffma2(acc[2][3], wp2, x1.y);
        ffma2(acc[3][0], wp3, x0.x); ffma2(acc[3][1], wp3, x0.y); ffma2(acc[3][2], wp3, x1.x); ffma2(acc[3][3], wp3, x1.y);
    }
}

// ---------------- one GEMM unit: 256 rows x 64 b over ktiles [ktb,kte), partial store ----------------
__device__ __forceinline__ void gemm_unit(const float* __restrict__ Wm, int rowBound,
                                          const float* __restrict__ X,
                                          float* __restrict__ dst,
                                          int row0, int ktb, int kte,
                                          float* sm, int tid, int rq, int bq)
{
    u64 acc[4][4] = {};
    float4 wv[4];
    float  xv[4];

    auto stage = [&](int kt) {
        int k0 = kt * KT;
#pragma unroll
        for (int u = 0; u < 4; u++) {
            int f4 = u * TPB + tid;
            int row = f4 >> 3, kq4 = f4 & 7;
            int gr = row0 + row, gk = k0 + kq4 * 4;
            float4 v = make_float4(0.f, 0.f, 0.f, 0.f);
            if (gr < rowBound) {
                if (gk + 3 < Hdim) v = *(const float4*)(Wm + (size_t)gr * Hdim + gk);
                else {
                    float* pv = (float*)&v;
#pragma unroll
                    for (int j = 0; j < 4; j++)
                        if (gk + j < Hdim) pv[j] = Wm[(size_t)gr * Hdim + gk + j];
                }
            }
            wv[u] = v;
        }
#pragma unroll
        for (int u = 0; u < 4; u++) {
            int idx = u * TPB + tid;
            int k = k0 + (idx >> 6);
            xv[u] = (k < Hdim) ? X[(size_t)k0 * 64 + idx] : 0.f;
        }
    };
    auto store_tile = [&](float* buf) {
#pragma unroll
        for (int u = 0; u < 4; u++) {
            int f4 = u * TPB + tid;
            int row = f4 >> 3, kq4 = f4 & 7;
            const float* pv = (const float*)&wv[u];
#pragma unroll
            for (int j = 0; j < 4; j++) {
                int k = kq4 * 4 + j;
                int col4 = (row >> 2) ^ (k & 7) ^ ((k >> 3) & 3);
                buf[k * 256 + col4 * 4 + (row & 3)] = pv[j];
            }
        }
#pragma unroll
        for (int u = 0; u < 4; u++) {
            int idx = u * TPB + tid;
            float v = xv[u];
            *(float2*)(buf + KT * 256 + 2 * idx) = make_float2(v, v);
        }
    };

    // prologue: tile ktb -> buf0; prefetch ktb+1 into regs
    stage(ktb);
    store_tile(sm);
    if (ktb + 1 < kte) stage(ktb + 1);
    __syncthreads();

    for (int kt = ktb; kt < kte; kt++) {
        float* cur = sm + ((kt - ktb) & 1) * BUFSTRIDE;
        float* nxt = sm + (((kt - ktb) + 1) & 1) * BUFSTRIDE;
        if (kt + 1 < kte) store_tile(nxt);   // regs hold tile kt+1
        if (kt + 2 < kte) stage(kt + 2);     // issue LDGs; land during mma
        mma_unit(acc, cur, cur + KT * 256, rq, bq);
        __syncthreads();
    }

    // writeback float4 partials (deterministic, no atomics)
#pragma unroll
    for (int rp = 0; rp < 4; rp++) {
        float2 v0 = unpack2(acc[rp][0]);
        float2 v1 = unpack2(acc[rp][1]);
        float2 v2 = unpack2(acc[rp][2]);
        float2 v3 = unpack2(acc[rp][3]);
        int r0 = row0 + rq * 8 + rp * 2;
        if (r0 < rowBound)
            *(float4*)(dst + (size_t)r0 * 64 + bq * 4) = make_float4(v0.x, v1.x, v2.x, v3.x);
        if (r0 + 1 < rowBound)
            *(float4*)(dst + (size_t)(r0 + 1) * 64 + bq * 4) = make_float4(v0.y, v1.y, v2.y, v3.y);
    }
}

// ---------------- persistent kernel ----------------
__global__ void __launch_bounds__(TPB, 1) uni_kernel(
    const int*   __restrict__ xb,
    const float* __restrict__ h0,    const float* __restrict__ c0,
    const float* __restrict__ etab,
    const float* __restrict__ w_mx,  const float* __restrict__ w_mh,
    const float* __restrict__ w_ih,  const float* __restrict__ w_hm,
    const float* __restrict__ bias,
    const float* __restrict__ w_lin, const float* __restrict__ b_lin,
    float* __restrict__ out)
{
    extern __shared__ __align__(16) float smem[];
    __shared__ int s_tok[Bsz];
    __shared__ int s_unit;

    const int tid = threadIdx.x;
    const int rq = (tid & 3) | (((tid >> 5) & 7) << 2);
    const int bq = ((tid >> 2) & 7) | ((tid >> 8) << 3);

    // ================= pre: tickets + token tables + state init + mxT =================
    if (blockIdx.x == 0 && tid == 0) { g_tkt1 = 0; g_tkt2 = 0; }
    for (int i = blockIdx.x * TPB + tid; i < NTOK * Hdim; i += gridDim.x * TPB) {
        int v = i / Hdim, j = i - v * Hdim;
        float a = 0.f;
        if (v != 0) {
#pragma unroll
            for (int e = 0; e < Edim; e++)
                a = fmaf(etab[(size_t)v * Edim + e], w_mx[(size_t)j * Edim + e], a);
        }
        g_mxtok[v][j] = a;
    }
    for (int i = blockIdx.x * TPB + tid; i < NTOK * Grows; i += gridDim.x * TPB) {
        int v = i / Grows, r = i - v * Grows;
        float a = bias[r];
        if (v != 0) {
#pragma unroll
            for (int e = 0; e < Edim; e++)
                a = fmaf(etab[(size_t)v * Edim + e], w_ih[(size_t)r * Edim + e], a);
        }
        g_gxtok[v][r] = a;
    }
    for (int i = blockIdx.x * TPB + tid; i < HB; i += gridDim.x * TPB) {
        int k = i >> 6, b = i & 63;
        g_hT[i] = h0[(size_t)b * Hdim + k];
        g_cT[i] = c0[(size_t)b * Hdim + k];
    }
    gbar();
    for (int unit = blockIdx.x; unit < Lseq; unit += gridDim.x) {
        __syncthreads();
        if (tid < Bsz) s_tok[tid] = xb[(size_t)tid * Lseq + unit];
        __syncthreads();
        float* dst = g_mxT + (size_t)unit * HB;
        for (int i = tid; i < HB; i += TPB) {
            int j = i >> 6, b = i & 63;
            dst[i] = g_mxtok[s_tok[b]][j];
        }
    }
    gbar();

    // ================= recurrent loop =================
    for (int t = 0; t < Lseq; t++) {
        // ---- P1: mdot partials = w_mh @ h (ticketed, no atomics) ----
        for (;;) {
            __syncthreads();
            if (tid == 0) s_unit = (int)atomicAdd(&g_tkt1, 1u);
            __syncthreads();
            int u = s_unit;
            if (u >= NU1) break;
            int rt = u / P1KS, ks = u - rt * P1KS;
            gemm_unit(w_mh, Hdim, g_hT, g_m1part[ks], rt * 256,
                      (ks * NKT) / P1KS, ((ks + 1) * NKT) / P1KS,
                      smem, tid, rq, bq);
        }
        gbar();

        // ---- P1.5: reduce mdot partials, fuse x2 = mdot*mx ----
        {
            const float4* mx4 = (const float4*)(g_mxT + (size_t)t * HB);
            float4* x24 = (float4*)g_x2T;
            for (int i = blockIdx.x * TPB + tid; i < HB / 4; i += gridDim.x * TPB) {
                float4 s = ((const float4*)g_m1part[0])[i];
#pragma unroll
                for (int ks = 1; ks < P1KS; ks++) {
                    float4 p = ((const float4*)g_m1part[ks])[i];
                    s.x += p.x; s.y += p.y; s.z += p.z; s.w += p.w;
                }
                float4 m = mx4[i];
                s.x *= m.x; s.y *= m.y; s.z *= m.z; s.w *= m.w;
                x24[i] = s;
            }
        }
        gbar();

        // ---- P2: gate partials = w_hm @ x2 (ticketed) ----
        if (blockIdx.x == 0 && tid == 0) g_tkt1 = 0;   // reset P1 ticket for next step
        for (;;) {
            __syncthreads();
            if (tid == 0) s_unit = (int)atomicAdd(&g_tkt2, 1u);
            __syncthreads();
            int u = s_unit;
            if (u >= NU2) break;
            int rt = u / P2KS, ks = u - rt * P2KS;
            gemm_unit(w_hm, Grows, g_x2T, g_gpart[ks], rt * 256,
                      ks * 5, ks * 5 + 5,
                      smem, tid, rq, bq);
        }
        gbar();

        // ---- P3: epilogue — sum partials + gxtok + c/h update (float4 over b) ----
        {
            if (blockIdx.x == 0 && tid == 0) g_tkt2 = 0;  // reset P2 ticket for next step
            if (tid < Bsz) s_tok[tid] = xb[(size_t)tid * Lseq + t];
            __syncthreads();
            for (int g = blockIdx.x * TPB + tid; g < HB / 4; g += gridDim.x * TPB) {
                int hj = g >> 4, b0 = (g & 15) * 4;
                int tk0 = s_tok[b0], tk1 = s_tok[b0 + 1], tk2 = s_tok[b0 + 2], tk3 = s_tok[b0 + 3];
                float4 gv[4];
#pragma unroll
                for (int gg = 0; gg < 4; gg++) {
                    int r = gg * Hdim + hj;
                    float4 a;
                    a.x = g_gxtok[tk0][r]; a.y = g_gxtok[tk1][r];
                    a.z = g_gxtok[tk2][r]; a.w = g_gxtok[tk3][r];
#pragma unroll
                    for (int ks = 0; ks < P2KS; ks++) {
                        float4 p = *(const float4*)(g_gpart[ks] + (size_t)r * 64 + b0);
                        a.x += p.x; a.y += p.y; a.z += p.z; a.w += p.w;
                    }
                    gv[gg] = a;
                }
                float4 c4 = ((const float4*)g_cT)[g];
                float4 h4;
                {
                    const float* pi = (const float*)&gv[0];
                    const float* pf = (const float*)&gv[1];
                    const float* pg = (const float*)&gv[2];
                    const float* po = (const float*)&gv[3];
                    float* pc = (float*)&c4;
                    float* ph = (float*)&h4;
#pragma unroll
                    for (int j = 0; j < 4; j++) {
                        float si = __fdividef(1.f, 1.f + __expf(-pi[j]));
                        float sf = __fdividef(1.f, 1.f + __expf(-pf[j]));
                        float so = __fdividef(1.f, 1.f + __expf(-po[j]));
                        float c = sf * pc[j] + si * tanhf(pg[j]);
                        pc[j] = c;
                        ph[j] = so * tanhf(c);
                    }
                }
                ((float4*)g_cT)[g] = c4;
                ((float4*)g_hT)[g] = h4;
                ((float4*)(g_hsT + (size_t)t * HB))[g] = h4;
            }
        }
        gbar();
    }

    // ================= final projection: out[b,t,n] = hs . w_lin[n,:] + b_lin ==============
    for (int unit = blockIdx.x; unit < Lseq; unit += gridDim.x) {
        const float* X = g_hsT + (size_t)unit * HB;
        float accv[4] = {};
        int b = tid & 63, ng = tid >> 6;   // ng 0..7
        float* sxf = smem;
        for (int kt = 0; kt < NKT; kt++) {
            int k0 = kt * KT;
            __syncthreads();
#pragma unroll
            for (int u = 0; u < 4; u++) {
                int idx = u * TPB + tid;
                int k = k0 + (idx >> 6);
                sxf[idx] = (k < Hdim) ? X[(size_t)k0 * 64 + idx] : 0.f;
            }
            __syncthreads();
            int klim = Hdim - k0; if (klim > KT) klim = KT;
            for (int kk = 0; kk < klim; kk++) {
                float xv = sxf[kk * 64 + b];
#pragma unroll
                for (int q = 0; q < 4; q++) {
                    int n = ng + q * 8;
                    if (n < NOUT) accv[q] = fmaf(xv, w_lin[(size_t)n * Hdim + k0 + kk], accv[q]);
                }
            }
        }
#pragma unroll
        for (int q = 0; q < 4; q++) {
            int n = ng + q * 8;
            if (n < NOUT)
                out[((size_t)b * Lseq + unit) * NOUT + n] = accv[q] + b_lin[n];
        }
    }
}

// ---------------- launcher: ONE graph node ----------------
extern "C" void kernel_launch(void* const* d_in, const int* in_sizes, int n_in,
                              void* d_out, int out_size)
{
    (void)in_sizes; (void)n_in; (void)out_size;
    const int*   xb    = (const int*)  d_in[0];
    // d_in[1] = xb_lens (unused by the reference math)
    const float* h0    = (const float*)d_in[2];
    const float* c0    = (const float*)d_in[3];
    const float* etab  = (const float*)d_in[4];
    const float* w_mx  = (const float*)d_in[5];
    const float* w_mh  = (const float*)d_in[6];
    const float* w_ih  = (const float*)d_in[7];
    const float* w_hm  = (const float*)d_in[8];
    const float* bias  = (const float*)d_in[9];
    const float* w_lin = (const float*)d_in[10];
    const float* b_lin = (const float*)d_in[11];
    float* out = (float*)d_out;

    static int smem_set = 0;
    if (!smem_set) {
        cudaFuncSetAttribute(uni_kernel, cudaFuncAttributeMaxDynamicSharedMemorySize, SMEM_BYTES);
        smem_set = 1;
    }

    int sms = 0;
    if (cudaDeviceGetAttribute(&sms, cudaDevAttrMultiProcessorCount, 0) != cudaSuccess || sms <= 0)
        sms = 148;

    uni_kernel<<<sms, TPB, SMEM_BYTES>>>(xb, h0, c0, etab, w_mx, w_mh, w_ih, w_hm,
                                         bias, w_lin, b_lin, out);
}

// round 9
// speedup vs baseline: 2.1628x; 1.2240x over previous
#include <cuda_runtime.h>
#include <cuda_bf16.h>
#include <math.h>
#include <stdint.h>

#define Bsz   64
#define Lseq  512
#define Edim  10
#define Hdim  1900
#define Grows 7600
#define NOUT  25
#define TPB   256
#define NTOK  30
#define KP    1920            // padded K (cols) of all images
#define KP_GATE 1920          // gate stride (rows) in W2 image
#define NK16  119             // k16 chunks covering 1900
#define R1P   2048            // padded rows, W1 image (8 rowtiles x 256)
#define R2P   7680            // padded rows, W2 image (30 rowtiles x 256)
#define P1KS  37
#define NU1   (8 * P1KS)      // 296 == 2*148
#define NU2   296
#define HB    (Hdim * Bsz)    // 121600

typedef unsigned int u32;
typedef unsigned short u16;

// ---------------- scratch (__device__ globals; no allocations) ----------------
static __device__ float g_mxT[(size_t)Lseq * HB];
static __device__ float g_hsT[(size_t)Lseq * HB];
static __device__ float g_cT[HB];
static __device__ float g_m1part[P1KS][R1P * Bsz];          // P1 k-split partials [row][b]
static __device__ float g_gpart[10][R2P * Bsz];             // P2 k-split partials [row][b]
static __device__ float g_mxtok[NTOK][Hdim];
static __device__ float g_gxtok[NTOK][Grows];
static __device__ __align__(16) u16 g_w1hi[(size_t)R1P * KP];   // w_mh bf16 images, row-major
static __device__ __align__(16) u16 g_w1lo[(size_t)R1P * KP];
static __device__ __align__(16) u16 g_w2hi[(size_t)R2P * KP];   // w_hm bf16 images
static __device__ __align__(16) u16 g_w2lo[(size_t)R2P * KP];
static __device__ __align__(16) u16 g_hhi[Bsz * KP];            // h transposed [b][k]
static __device__ __align__(16) u16 g_hlo[Bsz * KP];
static __device__ __align__(16) u16 g_xhi[Bsz * KP];            // x2 transposed [b][k]
static __device__ __align__(16) u16 g_xlo[Bsz * KP];
static __device__ volatile unsigned g_arrive;
static __device__ unsigned g_cnt;
static __device__ volatile unsigned g_gen;

// ---------------- helpers ----------------
__device__ __forceinline__ void bsplit(float v, u16& hi, u16& lo) {
    __nv_bfloat16 h = __float2bfloat16(v);
    hi = *reinterpret_cast<u16*>(&h);
    __nv_bfloat16 l = __float2bfloat16(v - __bfloat162float(h));
    lo = *reinterpret_cast<u16*>(&l);
}

__device__ __forceinline__ void mma_bf16(float d[4], const u32 a[4], const u32 b[2]) {
    asm volatile(
        "mma.sync.aligned.m16n8k16.row.col.f32.bf16.bf16.f32 "
        "{%0,%1,%2,%3}, {%4,%5,%6,%7}, {%8,%9}, {%0,%1,%2,%3};"
        : "+f"(d[0]), "+f"(d[1]), "+f"(d[2]), "+f"(d[3])
        : "r"(a[0]), "r"(a[1]), "r"(a[2]), "r"(a[3]), "r"(b[0]), "r"(b[1]));
}

// ---------------- barriers ----------------
__device__ __forceinline__ void gbarf(unsigned& ep) {
    __syncthreads();
    ep += 1;
    if (threadIdx.x == 0) {
        unsigned tgt = ep * (unsigned)gridDim.x;
        __threadfence();
        atomicAdd((unsigned*)&g_arrive, 1u);
        while ((int)(g_arrive - tgt) < 0) __nanosleep(32);
        __threadfence();
    }
    __syncthreads();
}
__device__ __forceinline__ void gbar_final() {   // resets g_arrive for next graph replay
    __syncthreads();
    if (threadIdx.x == 0) {
        unsigned gen = g_gen;
        __threadfence();
        if (atomicAdd(&g_cnt, 1u) == gridDim.x - 1) {
            g_cnt = 0;
            g_arrive = 0;
            __threadfence();
            g_gen = gen + 1;
        } else {
            while (g_gen == gen) __nanosleep(32);
        }
        __threadfence();
    }
    __syncthreads();
}

// ---------------- warp GEMM: 32 rows x 64 b over k16 chunks [kb0,kb1), split-bf16 ----------------
__device__ __forceinline__ void tc_warp(const u16* __restrict__ Whi, const u16* __restrict__ Wlo,
                                        const u16* __restrict__ Bhi, const u16* __restrict__ Blo,
                                        float* __restrict__ dst,
                                        int rbase, int kb0, int kb1)
{
    const int lane = threadIdx.x & 31;
    const int g = lane >> 2, t4 = lane & 3;
    float d[2][8][4];
#pragma unroll
    for (int m = 0; m < 2; m++)
#pragma unroll
        for (int n = 0; n < 8; n++)
#pragma unroll
            for (int q = 0; q < 4; q++) d[m][n][q] = 0.f;

    const size_t ro0 = (size_t)(rbase + g) * KP;
    const size_t ro1 = (size_t)(rbase + 16 + g) * KP;
    const int koff = 2 * t4;

    for (int kc = kb0; kc < kb1; kc++) {
        const int k0 = kc * 16 + koff;
        u32 ah[2][4], al[2][4], bh[8][2], bl[8][2];
        {
            size_t o = ro0 + k0;
            ah[0][0] = *(const u32*)(Whi + o);
            ah[0][1] = *(const u32*)(Whi + o + 8 * KP);
            ah[0][2] = *(const u32*)(Whi + o + 8);
            ah[0][3] = *(const u32*)(Whi + o + 8 * KP + 8);
            al[0][0] = *(const u32*)(Wlo + o);
            al[0][1] = *(const u32*)(Wlo + o + 8 * KP);
            al[0][2] = *(const u32*)(Wlo + o + 8);
            al[0][3] = *(const u32*)(Wlo + o + 8 * KP + 8);
            o = ro1 + k0;
            ah[1][0] = *(const u32*)(Whi + o);
            ah[1][1] = *(const u32*)(Whi + o + 8 * KP);
            ah[1][2] = *(const u32*)(Whi + o + 8);
            ah[1][3] = *(const u32*)(Whi + o + 8 * KP + 8);
            al[1][0] = *(const u32*)(Wlo + o);
            al[1][1] = *(const u32*)(Wlo + o + 8 * KP);
            al[1][2] = *(const u32*)(Wlo + o + 8);
            al[1][3] = *(const u32*)(Wlo + o + 8 * KP + 8);
        }
#pragma unroll
        for (int n = 0; n < 8; n++) {
            size_t o = (size_t)(n * 8 + g) * KP + k0;
            bh[n][0] = *(const u32*)(Bhi + o);
            bh[n][1] = *(const u32*)(Bhi + o + 8);
            bl[n][0] = *(const u32*)(Blo + o);
            bl[n][1] = *(const u32*)(Blo + o + 8);
        }
#pragma unroll
        for (int m = 0; m < 2; m++)
#pragma unroll
            for (int n = 0; n < 8; n++) {
                mma_bf16(d[m][n], ah[m], bh[n]);
                mma_bf16(d[m][n], ah[m], bl[n]);
                mma_bf16(d[m][n], al[m], bh[n]);
            }
    }
#pragma unroll
    for (int m = 0; m < 2; m++) {
        int r = rbase + m * 16 + g;
#pragma unroll
        for (int n = 0; n < 8; n++) {
            *(float2*)(dst + (size_t)r * 64 + n * 8 + 2 * t4)       = make_float2(d[m][n][0], d[m][n][1]);
            *(float2*)(dst + (size_t)(r + 8) * 64 + n * 8 + 2 * t4) = make_float2(d[m][n][2], d[m][n][3]);
        }
    }
}

// ---------------- persistent kernel ----------------
__global__ void __launch_bounds__(TPB, 1) uni_kernel(
    const int*   __restrict__ xb,
    const float* __restrict__ h0,    const float* __restrict__ c0,
    const float* __restrict__ etab,
    const float* __restrict__ w_mx,  const float* __restrict__ w_mh,
    const float* __restrict__ w_ih,  const float* __restrict__ w_hm,
    const float* __restrict__ bias,
    const float* __restrict__ w_lin, const float* __restrict__ b_lin,
    float* __restrict__ out)
{
    __shared__ float s_proj[2048];
    __shared__ int s_tok[Bsz];

    const int tid = threadIdx.x;
    const int wid = tid >> 5;
    const int gid = blockIdx.x * TPB + tid;
    const int gstride = gridDim.x * TPB;
    unsigned ep = 0;

    // ================= pre phase A =================
    for (int i = gid; i < NTOK * Hdim; i += gstride) {
        int v = i / Hdim, j = i - v * Hdim;
        float a = 0.f;
        if (v != 0)
#pragma unroll
            for (int e = 0; e < Edim; e++)
                a = fmaf(etab[(size_t)v * Edim + e], w_mx[(size_t)j * Edim + e], a);
        g_mxtok[v][j] = a;
    }
    for (int i = gid; i < NTOK * Grows; i += gstride) {
        int v = i / Grows, r = i - v * Grows;
        float a = bias[r];
        if (v != 0)
#pragma unroll
            for (int e = 0; e < Edim; e++)
                a = fmaf(etab[(size_t)v * Edim + e], w_ih[(size_t)r * Edim + e], a);
        g_gxtok[v][r] = a;
    }
    for (int i = gid; i < HB; i += gstride) {
        int j = i >> 6, b = i & 63;
        g_cT[i] = c0[(size_t)b * Hdim + j];
    }
    for (int i = gid; i < Bsz * KP; i += gstride) {
        int b = i / KP, j = i - b * KP;
        u16 hi = 0, lo = 0;
        if (j < Hdim) bsplit(h0[(size_t)b * Hdim + j], hi, lo);
        g_hhi[i] = hi; g_hlo[i] = lo;
        g_xhi[i] = 0;  g_xlo[i] = 0;
    }
    for (int i = gid; i < R2P * Bsz; i += gstride) g_gpart[9][i] = 0.f;
    for (size_t i = gid; i < (size_t)R1P * KP; i += gstride) {
        int row = (int)(i / KP), col = (int)(i - (size_t)row * KP);
        float v = (row < Hdim && col < Hdim) ? w_mh[(size_t)row * Hdim + col] : 0.f;
        u16 hi, lo; bsplit(v, hi, lo);
        g_w1hi[i] = hi; g_w1lo[i] = lo;
    }
    for (size_t i = gid; i < (size_t)R2P * KP; i += gstride) {
        int row = (int)(i / KP), col = (int)(i - (size_t)row * KP);
        int gate = row / KP_GATE, hj = row - gate * KP_GATE;
        float v = 0.f;
        if (hj < Hdim && col < Hdim)
            v = w_hm[((size_t)gate * Hdim + hj) * Hdim + col];
        u16 hi, lo; bsplit(v, hi, lo);
        g_w2hi[i] = hi; g_w2lo[i] = lo;
    }
    gbarf(ep);

    // ================= pre phase B: mxT =================
    for (int unit = blockIdx.x; unit < Lseq; unit += gridDim.x) {
        __syncthreads();
        if (tid < Bsz) s_tok[tid] = xb[(size_t)tid * Lseq + unit];
        __syncthreads();
        float* dst = g_mxT + (size_t)unit * HB;
        for (int i = tid; i < HB; i += TPB) {
            int j = i >> 6, b = i & 63;
            dst[i] = g_mxtok[s_tok[b]][j];
        }
    }
    gbarf(ep);

    // ================= recurrent loop =================
    for (int t = 0; t < Lseq; t++) {
        for (int u = blockIdx.x; u < NU1; u += gridDim.x) {
            int rt = u / P1KS, ks = u - rt * P1KS;
            int kb0 = (ks * NK16) / P1KS, kb1 = ((ks + 1) * NK16) / P1KS;
            tc_warp(g_w1hi, g_w1lo, g_hhi, g_hlo, g_m1part[ks],
                    rt * 256 + wid * 32, kb0, kb1);
        }
        gbarf(ep);

        {
            const float4* mx4 = (const float4*)(g_mxT + (size_t)t * HB);
            for (int i = gid; i < HB / 4; i += gstride) {
                float4 s = ((const float4*)g_m1part[0])[i];
#pragma unroll
                for (int ks = 1; ks < P1KS; ks++) {
                    float4 p = ((const float4*)g_m1part[ks])[i];
                    s.x += p.x; s.y += p.y; s.z += p.z; s.w += p.w;
                }
                float4 m = mx4[i];
                s.x *= m.x; s.y *= m.y; s.z *= m.z; s.w *= m.w;
                int j = i >> 4, b0 = (i & 15) * 4;
                const float* ps = (const float*)&s;
#pragma unroll
                for (int q = 0; q < 4; q++) {
                    u16 hi, lo; bsplit(ps[q], hi, lo);
                    int p = (b0 + q) * KP + j;
                    g_xhi[p] = hi; g_xlo[p] = lo;
                }
            }
        }
        gbarf(ep);

        for (int u = blockIdx.x; u < NU2; u += gridDim.x) {
            int ks = u / 30, rt = u - ks * 30;
            int nks = (rt < 26) ? 10 : 9;
            int kb0 = (ks * NK16) / nks, kb1 = ((ks + 1) * NK16) / nks;
            tc_warp(g_w2hi, g_w2lo, g_xhi, g_xlo, g_gpart[ks],
                    rt * 256 + wid * 32, kb0, kb1);
        }
        gbarf(ep);

        {
            __syncthreads();
            if (tid < Bsz) s_tok[tid] = xb[(size_t)tid * Lseq + t];
            __syncthreads();
            float* hs = g_hsT + (size_t)t * HB;
            for (int i = gid; i < HB / 4; i += gstride) {
                int hj = i >> 4, b0 = (i & 15) * 4;
                float4 gv[4];
#pragma unroll
                for (int gg = 0; gg < 4; gg++) {
                    int r = gg * KP_GATE + hj;
                    float4 a;
                    a.x = g_gxtok[s_tok[b0]][gg * Hdim + hj];
                    a.y = g_gxtok[s_tok[b0 + 1]][gg * Hdim + hj];
                    a.z = g_gxtok[s_tok[b0 + 2]][gg * Hdim + hj];
                    a.w = g_gxtok[s_tok[b0 + 3]][gg * Hdim + hj];
#pragma unroll
                    for (int ks = 0; ks < 10; ks++) {
                        float4 p = *(const float4*)(g_gpart[ks] + (size_t)r * 64 + b0);
                        a.x += p.x; a.y += p.y; a.z += p.z; a.w += p.w;
                    }
                    gv[gg] = a;
                }
                float4 c4 = ((const float4*)g_cT)[i];
                float4 h4;
                const float* pi = (const float*)&gv[0];
                const float* pf = (const float*)&gv[1];
                const float* pg = (const float*)&gv[2];
                const float* po = (const float*)&gv[3];
                float* pc = (float*)&c4;
                float* ph = (float*)&h4;
#pragma unroll
                for (int q = 0; q < 4; q++) {
                    float si = __fdividef(1.f, 1.f + __expf(-pi[q]));
                    float sf = __fdividef(1.f, 1.f + __expf(-pf[q]));
                    float so = __fdividef(1.f, 1.f + __expf(-po[q]));
                    float c = sf * pc[q] + si * tanhf(pg[q]);
                    pc[q] = c;
                    float h = so * tanhf(c);
                    ph[q] = h;
                    u16 hi, lo; bsplit(h, hi, lo);
                    int p = (b0 + q) * KP + hj;
                    g_hhi[p] = hi; g_hlo[p] = lo;
                }
                ((float4*)g_cT)[i] = c4;
                ((float4*)hs)[i] = h4;
            }
        }
        gbarf(ep);
    }
    gbar_final();

    // ================= final projection =================
    for (int unit = blockIdx.x; unit < Lseq; unit += gridDim.x) {
        const float* X = g_hsT + (size_t)unit * HB;
        float acc[7];
#pragma unroll
        for (int q = 0; q < 7; q++) acc[q] = 0.f;
        int b = tid & 63, ng = tid >> 6;
        for (int kt = 0; kt < 60; kt++) {
            int k0 = kt * 32;
            __syncthreads();
#pragma unroll
            for (int u = 0; u < 8; u++) {
                int idx = u * TPB + tid;
                int k = k0 + (idx >> 6);
                s_proj[idx] = (k < Hdim) ? X[(size_t)k0 * 64 + idx] : 0.f;
            }
            __syncthreads();
            int klim = Hdim - k0; if (klim > 32) klim = 32;
            for (int kk = 0; kk < klim; kk++) {
                float xv = s_proj[kk * 64 + b];
#pragma unroll
                for (int q = 0; q < 7; q++) {
                    int n = ng + q * 4;
                    if (n < NOUT) acc[q] = fmaf(xv, w_lin[(size_t)n * Hdim + k0 + kk], acc[q]);
                }
            }
        }
#pragma unroll
        for (int q = 0; q < 7; q++) {
            int n = ng + q * 4;
            if (n < NOUT)
                out[((size_t)b * Lseq + unit) * NOUT + n] = acc[q] + b_lin[n];
        }
    }
}

// ---------------- launcher: ONE graph node ----------------
extern "C" void kernel_launch(void* const* d_in, const int* in_sizes, int n_in,
                              void* d_out, int out_size)
{
    (void)in_sizes; (void)n_in; (void)out_size;
    const int*   xb    = (const int*)  d_in[0];
    // d_in[1] = xb_lens (unused by the reference math)
    const float* h0    = (const float*)d_in[2];
    const float* c0    = (const float*)d_in[3];
    const float* etab  = (const float*)d_in[4];
    const float* w_mx  = (const float*)d_in[5];
    const float* w_mh  = (const float*)d_in[6];
    const float* w_ih  = (const float*)d_in[7];
    const float* w_hm  = (const float*)d_in[8];
    const float* bias  = (const float*)d_in[9];
    const float* w_lin = (const float*)d_in[10];
    const float* b_lin = (const float*)d_in[11];
    float* out = (float*)d_out;

    int sms = 0;
    if (cudaDeviceGetAttribute(&sms, cudaDevAttrMultiProcessorCount, 0) != cudaSuccess || sms <= 0)
        sms = 148;

    uni_kernel<<<sms, TPB>>>(xb, h0, c0, etab, w_mx, w_mh, w_ih, w_hm,
                             bias, w_lin, b_lin, out);
}

// round 10
// speedup vs baseline: 3.6054x; 1.6670x over previous
#include <cuda_runtime.h>
#include <cuda_bf16.h>
#include <math.h>
#include <stdint.h>

#define Bsz   64
#define Lseq  512
#define Edim  10
#define Hdim  1900
#define Grows 7600
#define NOUT  25
#define TPB   256
#define NTOK  30
#define KP_GATE 1920          // gate stride (rows) in W2 image space
#define NKC   119             // k16 chunks covering 1900
#define R1P   2048            // padded rows, W1 image space (8 rowtiles x 256)
#define R2P   7680            // padded rows, W2 image space (30 rowtiles x 256)
#define A1T   (R1P / 16)      // 128 m16 tiles
#define A2T   (R2P / 16)      // 480 m16 tiles
#define P1KS  18
#define NU1   (8 * P1KS)      // 144
#define NU2   296
#define HB    (Hdim * Bsz)    // 121600

typedef unsigned int u32;
typedef unsigned short u16;

// ---------------- scratch (__device__ globals; no allocations) ----------------
static __device__ float g_mxT[(size_t)Lseq * HB];
static __device__ float g_hsT[(size_t)Lseq * HB];
static __device__ float g_cT[HB];
static __device__ float g_m1part[P1KS][R1P * Bsz];            // P1 k-split partials [row][b]
static __device__ float g_gpart[10][R2P * Bsz];               // P2 k-split partials [row][b]
static __device__ float g_mxtok[NTOK][Hdim];
static __device__ float g_gxtok[NTOK][Grows];
// fragment-packed operand images (u16 bf16), layout [tile][kc][lane][8 u16]
static __device__ __align__(16) u16 g_w1hi[(size_t)A1T * NKC * 256];
static __device__ __align__(16) u16 g_w1lo[(size_t)A1T * NKC * 256];
static __device__ __align__(16) u16 g_w2hi[(size_t)A2T * NKC * 256];
static __device__ __align__(16) u16 g_w2lo[(size_t)A2T * NKC * 256];
static __device__ __align__(16) u16 g_hpk[8 * NKC * 256];     // h packed (hi+lo interleaved)
static __device__ __align__(16) u16 g_xpk[8 * NKC * 256];     // x2 packed
static __device__ volatile unsigned g_arrive;
static __device__ unsigned g_cnt;
static __device__ volatile unsigned g_gen;

// ---------------- helpers ----------------
__device__ __forceinline__ void bsplit(float v, u16& hi, u16& lo) {
    __nv_bfloat16 h = __float2bfloat16(v);
    hi = *reinterpret_cast<u16*>(&h);
    __nv_bfloat16 l = __float2bfloat16(v - __bfloat162float(h));
    lo = *reinterpret_cast<u16*>(&l);
}
__device__ __forceinline__ void mma_bf16(float d[4], const u32 a0, const u32 a1, const u32 a2, const u32 a3,
                                         const u32 b0, const u32 b1) {
    asm volatile(
        "mma.sync.aligned.m16n8k16.row.col.f32.bf16.bf16.f32 "
        "{%0,%1,%2,%3}, {%4,%5,%6,%7}, {%8,%9}, {%0,%1,%2,%3};"
        : "+f"(d[0]), "+f"(d[1]), "+f"(d[2]), "+f"(d[3])
        : "r"(a0), "r"(a1), "r"(a2), "r"(a3), "r"(b0), "r"(b1));
}
// packed u16 index for B-style images: element (b, k), hi part (+4 for lo)
__device__ __forceinline__ int bpk_idx(int b, int k) {
    return ((((b >> 3) * NKC + (k >> 4)) * 32 + 4 * (b & 7) + ((k & 7) >> 1)) << 3)
           + (((k >> 3) & 1) << 1) + (k & 1);
}

// ---------------- barriers ----------------
__device__ __forceinline__ void gbarf(unsigned& ep) {
    __syncthreads();
    ep += 1;
    if (threadIdx.x == 0) {
        unsigned tgt = ep * (unsigned)gridDim.x;
        __threadfence();
        atomicAdd((unsigned*)&g_arrive, 1u);
        while ((int)(g_arrive - tgt) < 0) __nanosleep(32);
        __threadfence();
    }
    __syncthreads();
}
__device__ __forceinline__ void gbar_final() {
    __syncthreads();
    if (threadIdx.x == 0) {
        unsigned gen = g_gen;
        __threadfence();
        if (atomicAdd(&g_cnt, 1u) == gridDim.x - 1) {
            g_cnt = 0;
            g_arrive = 0;
            __threadfence();
            g_gen = gen + 1;
        } else {
            while (g_gen == gen) __nanosleep(32);
        }
        __threadfence();
    }
    __syncthreads();
}

// ---------------- warp GEMM: 32 rows x 64 b over k16 chunks [kb0,kb1) ----------------
// A images fragment-packed (separate hi/lo); B image packs hi+lo in one uint4.
__device__ __forceinline__ void tc_warp(const u16* __restrict__ Whi, const u16* __restrict__ Wlo,
                                        const u16* __restrict__ Bpk,
                                        float* __restrict__ dst,
                                        int rbase, int kb0, int kb1)
{
    const int lane = threadIdx.x & 31;
    const int g = lane >> 2, t4 = lane & 3;
    const int mt0 = rbase >> 4;          // two m16 tiles: mt0, mt0+1
    const uint4* Ah = (const uint4*)Whi;
    const uint4* Al = (const uint4*)Wlo;
    const uint4* Bp = (const uint4*)Bpk;

    float d[2][8][4];
#pragma unroll
    for (int m = 0; m < 2; m++)
#pragma unroll
        for (int n = 0; n < 8; n++)
#pragma unroll
            for (int q = 0; q < 4; q++) d[m][n][q] = 0.f;

    for (int kc = kb0; kc < kb1; kc++) {
        uint4 ah[2], al[2], bp[8];
#pragma unroll
        for (int m = 0; m < 2; m++) {
            size_t o = ((size_t)(mt0 + m) * NKC + kc) * 32 + lane;
            ah[m] = Ah[o];
            al[m] = Al[o];
        }
#pragma unroll
        for (int n = 0; n < 8; n++)
            bp[n] = Bp[((size_t)n * NKC + kc) * 32 + lane];
#pragma unroll
        for (int m = 0; m < 2; m++)
#pragma unroll
            for (int n = 0; n < 8; n++) {
                mma_bf16(d[m][n], ah[m].x, ah[m].y, ah[m].z, ah[m].w, bp[n].x, bp[n].y); // hi*hi
                mma_bf16(d[m][n], ah[m].x, ah[m].y, ah[m].z, ah[m].w, bp[n].z, bp[n].w); // hi*lo
                mma_bf16(d[m][n], al[m].x, al[m].y, al[m].z, al[m].w, bp[n].x, bp[n].y); // lo*hi
            }
    }
#pragma unroll
    for (int m = 0; m < 2; m++) {
        int r = rbase + m * 16 + g;
#pragma unroll
        for (int n = 0; n < 8; n++) {
            *(float2*)(dst + (size_t)r * 64 + n * 8 + 2 * t4)       = make_float2(d[m][n][0], d[m][n][1]);
            *(float2*)(dst + (size_t)(r + 8) * 64 + n * 8 + 2 * t4) = make_float2(d[m][n][2], d[m][n][3]);
        }
    }
}

// ---------------- persistent kernel ----------------
__global__ void __launch_bounds__(TPB, 1) uni_kernel(
    const int*   __restrict__ xb,
    const float* __restrict__ h0,    const float* __restrict__ c0,
    const float* __restrict__ etab,
    const float* __restrict__ w_mx,  const float* __restrict__ w_mh,
    const float* __restrict__ w_ih,  const float* __restrict__ w_hm,
    const float* __restrict__ bias,
    const float* __restrict__ w_lin, const float* __restrict__ b_lin,
    float* __restrict__ out)
{
    __shared__ float s_proj[2048];
    __shared__ int s_tok[Bsz];

    const int tid = threadIdx.x;
    const int wid = tid >> 5;
    const int gid = blockIdx.x * TPB + tid;
    const int gstride = gridDim.x * TPB;
    unsigned ep = 0;

    // ================= pre phase A =================
    for (int i = gid; i < NTOK * Hdim; i += gstride) {
        int v = i / Hdim, j = i - v * Hdim;
        float a = 0.f;
        if (v != 0)
#pragma unroll
            for (int e = 0; e < Edim; e++)
                a = fmaf(etab[(size_t)v * Edim + e], w_mx[(size_t)j * Edim + e], a);
        g_mxtok[v][j] = a;
    }
    for (int i = gid; i < NTOK * Grows; i += gstride) {
        int v = i / Grows, r = i - v * Grows;
        float a = bias[r];
        if (v != 0)
#pragma unroll
            for (int e = 0; e < Edim; e++)
                a = fmaf(etab[(size_t)v * Edim + e], w_ih[(size_t)r * Edim + e], a);
        g_gxtok[v][r] = a;
    }
    for (int i = gid; i < HB; i += gstride) {
        int j = i >> 6, b = i & 63;
        g_cT[i] = c0[(size_t)b * Hdim + j];
    }
    // zero + fill packed h image; zero packed x image
    for (int i = gid; i < 8 * NKC * 256; i += gstride) { g_hpk[i] = 0; g_xpk[i] = 0; }
    gbarf(ep);
    for (int i = gid; i < HB; i += gstride) {
        int j = i >> 6, b = i & 63;
        u16 hi, lo; bsplit(h0[(size_t)b * Hdim + j], hi, lo);
        int p = bpk_idx(b, j);
        g_hpk[p] = hi; g_hpk[p + 4] = lo;
    }
    for (int i = gid; i < R2P * Bsz; i += gstride) g_gpart[9][i] = 0.f;
    // W1 fragment-packed image (w_mh)
    for (size_t i = gid; i < (size_t)A1T * NKC * 256; i += gstride) {
        int mt = (int)(i / (NKC * 256));
        int rem = (int)(i - (size_t)mt * (NKC * 256));
        int kc = rem >> 8, r2 = rem & 255;
        int lane = r2 >> 3, e = r2 & 7;
        int g = lane >> 2, t4 = lane & 3;
        int q = e >> 1, bit = e & 1;
        int row = mt * 16 + g + ((q & 1) ? 8 : 0);
        int col = kc * 16 + 2 * t4 + ((q & 2) ? 8 : 0) + bit;
        float v = (row < Hdim && col < Hdim) ? w_mh[(size_t)row * Hdim + col] : 0.f;
        u16 hi, lo; bsplit(v, hi, lo);
        g_w1hi[i] = hi; g_w1lo[i] = lo;
    }
    // W2 fragment-packed image (w_hm); image row = gate*1920 + hj
    for (size_t i = gid; i < (size_t)A2T * NKC * 256; i += gstride) {
        int mt = (int)(i / (NKC * 256));
        int rem = (int)(i - (size_t)mt * (NKC * 256));
        int kc = rem >> 8, r2 = rem & 255;
        int lane = r2 >> 3, e = r2 & 7;
        int g = lane >> 2, t4 = lane & 3;
        int q = e >> 1, bit = e & 1;
        int row = mt * 16 + g + ((q & 1) ? 8 : 0);
        int col = kc * 16 + 2 * t4 + ((q & 2) ? 8 : 0) + bit;
        int gate = row / KP_GATE, hj = row - gate * KP_GATE;
        float v = 0.f;
        if (hj < Hdim && col < Hdim)
            v = w_hm[((size_t)gate * Hdim + hj) * Hdim + col];
        u16 hi, lo; bsplit(v, hi, lo);
        g_w2hi[i] = hi; g_w2lo[i] = lo;
    }
    gbarf(ep);

    // ================= pre phase B: mxT =================
    for (int unit = blockIdx.x; unit < Lseq; unit += gridDim.x) {
        __syncthreads();
        if (tid < Bsz) s_tok[tid] = xb[(size_t)tid * Lseq + unit];
        __syncthreads();
        float* dst = g_mxT + (size_t)unit * HB;
        for (int i = tid; i < HB; i += TPB) {
            int j = i >> 6, b = i & 63;
            dst[i] = g_mxtok[s_tok[b]][j];
        }
    }
    gbarf(ep);

    // ================= recurrent loop =================
    for (int t = 0; t < Lseq; t++) {
        // ---- P1: mdot partials = w_mh @ h (144 units: 8 rowtiles x 18 ksplits) ----
        for (int u = blockIdx.x; u < NU1; u += gridDim.x) {
            int rt = u / P1KS, ks = u - rt * P1KS;
            int kb0 = (ks * NKC) / P1KS, kb1 = ((ks + 1) * NKC) / P1KS;
            tc_warp(g_w1hi, g_w1lo, g_hpk, g_m1part[ks],
                    rt * 256 + wid * 32, kb0, kb1);
        }
        gbarf(ep);

        // ---- P1.5: reduce partials, x2 = mdot*mx, scatter into packed x image ----
        {
            const float4* mx4 = (const float4*)(g_mxT + (size_t)t * HB);
            for (int i = gid; i < HB / 4; i += gstride) {
                float4 s = ((const float4*)g_m1part[0])[i];
#pragma unroll
                for (int ks = 1; ks < P1KS; ks++) {
                    float4 p = ((const float4*)g_m1part[ks])[i];
                    s.x += p.x; s.y += p.y; s.z += p.z; s.w += p.w;
                }
                float4 m = mx4[i];
                s.x *= m.x; s.y *= m.y; s.z *= m.z; s.w *= m.w;
                int j = i >> 4, b0 = (i & 15) * 4;
                const float* ps = (const float*)&s;
#pragma unroll
                for (int q = 0; q < 4; q++) {
                    u16 hi, lo; bsplit(ps[q], hi, lo);
                    int p = bpk_idx(b0 + q, j);
                    g_xpk[p] = hi; g_xpk[p + 4] = lo;
                }
            }
        }
        gbarf(ep);

        // ---- P2: gate partials = w_hm @ x2 (296 ragged units over 30 rowtiles) ----
        for (int u = blockIdx.x; u < NU2; u += gridDim.x) {
            int ks = u / 30, rt = u - ks * 30;
            int nks = (rt < 26) ? 10 : 9;
            int kb0 = (ks * NKC) / nks, kb1 = ((ks + 1) * NKC) / nks;
            tc_warp(g_w2hi, g_w2lo, g_xpk, g_gpart[ks],
                    rt * 256 + wid * 32, kb0, kb1);
        }
        gbarf(ep);

        // ---- P3: gates + c/h update + hs + packed h scatter ----
        {
            __syncthreads();
            if (tid < Bsz) s_tok[tid] = xb[(size_t)tid * Lseq + t];
            __syncthreads();
            float* hs = g_hsT + (size_t)t * HB;
            for (int i = gid; i < HB / 4; i += gstride) {
                int hj = i >> 4, b0 = (i & 15) * 4;
                float4 gv[4];
#pragma unroll
                for (int gg = 0; gg < 4; gg++) {
                    int r = gg * KP_GATE + hj;
                    float4 a;
                    a.x = g_gxtok[s_tok[b0]][gg * Hdim + hj];
                    a.y = g_gxtok[s_tok[b0 + 1]][gg * Hdim + hj];
                    a.z = g_gxtok[s_tok[b0 + 2]][gg * Hdim + hj];
                    a.w = g_gxtok[s_tok[b0 + 3]][gg * Hdim + hj];
#pragma unroll
                    for (int ks = 0; ks < 10; ks++) {
                        float4 p = *(const float4*)(g_gpart[ks] + (size_t)r * 64 + b0);
                        a.x += p.x; a.y += p.y; a.z += p.z; a.w += p.w;
                    }
                    gv[gg] = a;
                }
                float4 c4 = ((const float4*)g_cT)[i];
                float4 h4;
                const float* pi = (const float*)&gv[0];
                const float* pf = (const float*)&gv[1];
                const float* pg = (const float*)&gv[2];
                const float* po = (const float*)&gv[3];
                float* pc = (float*)&c4;
                float* ph = (float*)&h4;
#pragma unroll
                for (int q = 0; q < 4; q++) {
                    float si = __fdividef(1.f, 1.f + __expf(-pi[q]));
                    float sf = __fdividef(1.f, 1.f + __expf(-pf[q]));
                    float so = __fdividef(1.f, 1.f + __expf(-po[q]));
                    float c = sf * pc[q] + si * tanhf(pg[q]);
                    pc[q] = c;
                    float h = so * tanhf(c);
                    ph[q] = h;
                    u16 hi, lo; bsplit(h, hi, lo);
                    int p = bpk_idx(b0 + q, hj);
                    g_hpk[p] = hi; g_hpk[p + 4] = lo;
                }
                ((float4*)g_cT)[i] = c4;
                ((float4*)hs)[i] = h4;
            }
        }
        gbarf(ep);
    }
    gbar_final();

    // ================= final projection =================
    for (int unit = blockIdx.x; unit < Lseq; unit += gridDim.x) {
        const float* X = g_hsT + (size_t)unit * HB;
        float acc[7];
#pragma unroll
        for (int q = 0; q < 7; q++) acc[q] = 0.f;
        int b = tid & 63, ng = tid >> 6;
        for (int kt = 0; kt < 60; kt++) {
            int k0 = kt * 32;
            __syncthreads();
#pragma unroll
            for (int u = 0; u < 8; u++) {
                int idx = u * TPB + tid;
                int k = k0 + (idx >> 6);
                s_proj[idx] = (k < Hdim) ? X[(size_t)k0 * 64 + idx] : 0.f;
            }
            __syncthreads();
            int klim = Hdim - k0; if (klim > 32) klim = 32;
            for (int kk = 0; kk < klim; kk++) {
                float xv = s_proj[kk * 64 + b];
#pragma unroll
                for (int q = 0; q < 7; q++) {
                    int n = ng + q * 4;
                    if (n < NOUT) acc[q] = fmaf(xv, w_lin[(size_t)n * Hdim + k0 + kk], acc[q]);
                }
            }
        }
#pragma unroll
        for (int q = 0; q < 7; q++) {
            int n = ng + q * 4;
            if (n < NOUT)
                out[((size_t)b * Lseq + unit) * NOUT + n] = acc[q] + b_lin[n];
        }
    }
}

// ---------------- launcher: ONE graph node ----------------
extern "C" void kernel_launch(void* const* d_in, const int* in_sizes, int n_in,
                              void* d_out, int out_size)
{
    (void)in_sizes; (void)n_in; (void)out_size;
    const int*   xb    = (const int*)  d_in[0];
    // d_in[1] = xb_lens (unused by the reference math)
    const float* h0    = (const float*)d_in[2];
    const float* c0    = (const float*)d_in[3];
    const float* etab  = (const float*)d_in[4];
    const float* w_mx  = (const float*)d_in[5];
    const float* w_mh  = (const float*)d_in[6];
    const float* w_ih  = (const float*)d_in[7];
    const float* w_hm  = (const float*)d_in[8];
    const float* bias  = (const float*)d_in[9];
    const float* w_lin = (const float*)d_in[10];
    const float* b_lin = (const float*)d_in[11];
    float* out = (float*)d_out;

    int sms = 0;
    if (cudaDeviceGetAttribute(&sms, cudaDevAttrMultiProcessorCount, 0) != cudaSuccess || sms <= 0)
        sms = 148;

    uni_kernel<<<sms, TPB>>>(xb, h0, c0, etab, w_mx, w_mh, w_ih, w_hm,
                             bias, w_lin, b_lin, out);
}

// round 11
// speedup vs baseline: 3.6368x; 1.0087x over previous
#include <cuda_runtime.h>
#include <cuda_bf16.h>
#include <math.h>
#include <stdint.h>

#define Bsz   64
#define Lseq  512
#define Edim  10
#define Hdim  1900
#define Grows 7600
#define NOUT  25
#define TPB   512
#define NTOK  30
#define KP_GATE 1920          // gate stride (rows) in W2 image space
#define NKC   119             // k16 chunks covering 1900
#define R1P   2048            // padded rows, W1 image space (8 rowtiles x 256)
#define R2P   7680            // padded rows, W2 image space (30 rowtiles x 256)
#define A1T   (R1P / 16)      // 128 m16 tiles
#define A2T   (R2P / 16)      // 480 m16 tiles
#define P1KS  18
#define NU1   (8 * P1KS)      // 144
#define NU2   296
#define HB    (Hdim * Bsz)    // 121600

typedef unsigned int u32;
typedef unsigned short u16;

// ---------------- scratch (__device__ globals; no allocations) ----------------
static __device__ float g_mxT[(size_t)Lseq * HB];
static __device__ float g_hsT[(size_t)Lseq * HB];
static __device__ float g_cT[HB];
static __device__ float g_m1part[P1KS][R1P * Bsz];            // P1 k-split partials [row][b]
static __device__ float g_gpart[10][R2P * Bsz];               // P2 k-split partials [row][b]
static __device__ float g_mxtok[NTOK][Hdim];
static __device__ float g_gxtok[NTOK][Grows];
// fragment-packed operand images (u16 bf16), layout [tile][kc][lane][8 u16]
static __device__ __align__(16) u16 g_w1hi[(size_t)A1T * NKC * 256];
static __device__ __align__(16) u16 g_w1lo[(size_t)A1T * NKC * 256];
static __device__ __align__(16) u16 g_w2hi[(size_t)A2T * NKC * 256];
static __device__ __align__(16) u16 g_w2lo[(size_t)A2T * NKC * 256];
static __device__ __align__(16) u16 g_hpk[8 * NKC * 256];     // h packed (hi+lo interleaved)
static __device__ __align__(16) u16 g_xpk[8 * NKC * 256];     // x2 packed
static __device__ volatile unsigned g_arrive;
static __device__ unsigned g_cnt;
static __device__ volatile unsigned g_gen;

// ---------------- helpers ----------------
__device__ __forceinline__ void bsplit(float v, u16& hi, u16& lo) {
    __nv_bfloat16 h = __float2bfloat16(v);
    hi = *reinterpret_cast<u16*>(&h);
    __nv_bfloat16 l = __float2bfloat16(v - __bfloat162float(h));
    lo = *reinterpret_cast<u16*>(&l);
}
__device__ __forceinline__ void mma_bf16(float d[4], const u32 a0, const u32 a1, const u32 a2, const u32 a3,
                                         const u32 b0, const u32 b1) {
    asm volatile(
        "mma.sync.aligned.m16n8k16.row.col.f32.bf16.bf16.f32 "
        "{%0,%1,%2,%3}, {%4,%5,%6,%7}, {%8,%9}, {%0,%1,%2,%3};"
        : "+f"(d[0]), "+f"(d[1]), "+f"(d[2]), "+f"(d[3])
        : "r"(a0), "r"(a1), "r"(a2), "r"(a3), "r"(b0), "r"(b1));
}
// packed u16 index for B-style images: element (b, k), hi part (+4 for lo)
__device__ __forceinline__ int bpk_idx(int b, int k) {
    return ((((b >> 3) * NKC + (k >> 4)) * 32 + 4 * (b & 7) + ((k & 7) >> 1)) << 3)
           + (((k >> 3) & 1) << 1) + (k & 1);
}

// ---------------- barriers ----------------
__device__ __forceinline__ void gbarf(unsigned& ep) {
    __syncthreads();
    ep += 1;
    if (threadIdx.x == 0) {
        unsigned tgt = ep * (unsigned)gridDim.x;
        __threadfence();
        atomicAdd((unsigned*)&g_arrive, 1u);
        while ((int)(g_arrive - tgt) < 0) __nanosleep(32);
        __threadfence();
    }
    __syncthreads();
}
__device__ __forceinline__ void gbar_final() {
    __syncthreads();
    if (threadIdx.x == 0) {
        unsigned gen = g_gen;
        __threadfence();
        if (atomicAdd(&g_cnt, 1u) == gridDim.x - 1) {
            g_cnt = 0;
            g_arrive = 0;
            __threadfence();
            g_gen = gen + 1;
        } else {
            while (g_gen == gen) __nanosleep(32);
        }
        __threadfence();
    }
    __syncthreads();
}

// ---------------- warp GEMM: 16 rows x 64 b over k16 chunks [kb0,kb1) ----------------
// A images fragment-packed (separate hi/lo); B image packs hi+lo in one uint4.
__device__ __forceinline__ void tc_warp(const u16* __restrict__ Whi, const u16* __restrict__ Wlo,
                                        const u16* __restrict__ Bpk,
                                        float* __restrict__ dst,
                                        int rbase, int kb0, int kb1)
{
    const int lane = threadIdx.x & 31;
    const int g = lane >> 2, t4 = lane & 3;
    const int mt = rbase >> 4;           // one m16 tile per warp
    const uint4* Ah = (const uint4*)Whi;
    const uint4* Al = (const uint4*)Wlo;
    const uint4* Bp = (const uint4*)Bpk;

    float d[8][4];
#pragma unroll
    for (int n = 0; n < 8; n++)
#pragma unroll
        for (int q = 0; q < 4; q++) d[n][q] = 0.f;

    for (int kc = kb0; kc < kb1; kc++) {
        uint4 ah, al, bp[8];
        {
            size_t o = ((size_t)mt * NKC + kc) * 32 + lane;
            ah = Ah[o];
            al = Al[o];
        }
#pragma unroll
        for (int n = 0; n < 8; n++)
            bp[n] = Bp[((size_t)n * NKC + kc) * 32 + lane];
#pragma unroll
        for (int n = 0; n < 8; n++) {
            mma_bf16(d[n], ah.x, ah.y, ah.z, ah.w, bp[n].x, bp[n].y); // hi*hi
            mma_bf16(d[n], ah.x, ah.y, ah.z, ah.w, bp[n].z, bp[n].w); // hi*lo
            mma_bf16(d[n], al.x, al.y, al.z, al.w, bp[n].x, bp[n].y); // lo*hi
        }
    }
    int r = rbase + g;
#pragma unroll
    for (int n = 0; n < 8; n++) {
        *(float2*)(dst + (size_t)r * 64 + n * 8 + 2 * t4)       = make_float2(d[n][0], d[n][1]);
        *(float2*)(dst + (size_t)(r + 8) * 64 + n * 8 + 2 * t4) = make_float2(d[n][2], d[n][3]);
    }
}

// ---------------- persistent kernel ----------------
__global__ void __launch_bounds__(TPB, 1) uni_kernel(
    const int*   __restrict__ xb,
    const float* __restrict__ h0,    const float* __restrict__ c0,
    const float* __restrict__ etab,
    const float* __restrict__ w_mx,  const float* __restrict__ w_mh,
    const float* __restrict__ w_ih,  const float* __restrict__ w_hm,
    const float* __restrict__ bias,
    const float* __restrict__ w_lin, const float* __restrict__ b_lin,
    float* __restrict__ out)
{
    __shared__ float s_proj[2048];
    __shared__ int s_tok[Bsz];

    const int tid = threadIdx.x;
    const int wid = tid >> 5;            // 0..15
    const int gid = blockIdx.x * TPB + tid;
    const int gstride = gridDim.x * TPB;
    unsigned ep = 0;

    // ================= pre phase A =================
    for (int i = gid; i < NTOK * Hdim; i += gstride) {
        int v = i / Hdim, j = i - v * Hdim;
        float a = 0.f;
        if (v != 0)
#pragma unroll
            for (int e = 0; e < Edim; e++)
                a = fmaf(etab[(size_t)v * Edim + e], w_mx[(size_t)j * Edim + e], a);
        g_mxtok[v][j] = a;
    }
    for (int i = gid; i < NTOK * Grows; i += gstride) {
        int v = i / Grows, r = i - v * Grows;
        float a = bias[r];
        if (v != 0)
#pragma unroll
            for (int e = 0; e < Edim; e++)
                a = fmaf(etab[(size_t)v * Edim + e], w_ih[(size_t)r * Edim + e], a);
        g_gxtok[v][r] = a;
    }
    for (int i = gid; i < HB; i += gstride) {
        int j = i >> 6, b = i & 63;
        g_cT[i] = c0[(size_t)b * Hdim + j];
    }
    for (int i = gid; i < 8 * NKC * 256; i += gstride) { g_hpk[i] = 0; g_xpk[i] = 0; }
    gbarf(ep);
    for (int i = gid; i < HB; i += gstride) {
        int j = i >> 6, b = i & 63;
        u16 hi, lo; bsplit(h0[(size_t)b * Hdim + j], hi, lo);
        int p = bpk_idx(b, j);
        g_hpk[p] = hi; g_hpk[p + 4] = lo;
    }
    for (int i = gid; i < R2P * Bsz; i += gstride) g_gpart[9][i] = 0.f;
    // W1 fragment-packed image (w_mh)
    for (size_t i = gid; i < (size_t)A1T * NKC * 256; i += gstride) {
        int mt = (int)(i / (NKC * 256));
        int rem = (int)(i - (size_t)mt * (NKC * 256));
        int kc = rem >> 8, r2 = rem & 255;
        int lane = r2 >> 3, e = r2 & 7;
        int g = lane >> 2, t4 = lane & 3;
        int q = e >> 1, bit = e & 1;
        int row = mt * 16 + g + ((q & 1) ? 8 : 0);
        int col = kc * 16 + 2 * t4 + ((q & 2) ? 8 : 0) + bit;
        float v = (row < Hdim && col < Hdim) ? w_mh[(size_t)row * Hdim + col] : 0.f;
        u16 hi, lo; bsplit(v, hi, lo);
        g_w1hi[i] = hi; g_w1lo[i] = lo;
    }
    // W2 fragment-packed image (w_hm); image row = gate*1920 + hj
    for (size_t i = gid; i < (size_t)A2T * NKC * 256; i += gstride) {
        int mt = (int)(i / (NKC * 256));
        int rem = (int)(i - (size_t)mt * (NKC * 256));
        int kc = rem >> 8, r2 = rem & 255;
        int lane = r2 >> 3, e = r2 & 7;
        int g = lane >> 2, t4 = lane & 3;
        int q = e >> 1, bit = e & 1;
        int row = mt * 16 + g + ((q & 1) ? 8 : 0);
        int col = kc * 16 + 2 * t4 + ((q & 2) ? 8 : 0) + bit;
        int gate = row / KP_GATE, hj = row - gate * KP_GATE;
        float v = 0.f;
        if (hj < Hdim && col < Hdim)
            v = w_hm[((size_t)gate * Hdim + hj) * Hdim + col];
        u16 hi, lo; bsplit(v, hi, lo);
        g_w2hi[i] = hi; g_w2lo[i] = lo;
    }
    gbarf(ep);

    // ================= pre phase B: mxT =================
    for (int unit = blockIdx.x; unit < Lseq; unit += gridDim.x) {
        __syncthreads();
        if (tid < Bsz) s_tok[tid] = xb[(size_t)tid * Lseq + unit];
        __syncthreads();
        float* dst = g_mxT + (size_t)unit * HB;
        for (int i = tid; i < HB; i += TPB) {
            int j = i >> 6, b = i & 63;
            dst[i] = g_mxtok[s_tok[b]][j];
        }
    }
    gbarf(ep);

    // ================= recurrent loop =================
    for (int t = 0; t < Lseq; t++) {
        // ---- P1: mdot partials = w_mh @ h (144 units: 8 rowtiles x 18 ksplits) ----
        for (int u = blockIdx.x; u < NU1; u += gridDim.x) {
            int rt = u / P1KS, ks = u - rt * P1KS;
            int kb0 = (ks * NKC) / P1KS, kb1 = ((ks + 1) * NKC) / P1KS;
            tc_warp(g_w1hi, g_w1lo, g_hpk, g_m1part[ks],
                    rt * 256 + wid * 16, kb0, kb1);
        }
        gbarf(ep);

        // ---- P1.5: reduce partials, x2 = mdot*mx, scatter into packed x image ----
        {
            const float4* mx4 = (const float4*)(g_mxT + (size_t)t * HB);
            for (int i = gid; i < HB / 4; i += gstride) {
                float4 s = ((const float4*)g_m1part[0])[i];
#pragma unroll
                for (int ks = 1; ks < P1KS; ks++) {
                    float4 p = ((const float4*)g_m1part[ks])[i];
                    s.x += p.x; s.y += p.y; s.z += p.z; s.w += p.w;
                }
                float4 m = mx4[i];
                s.x *= m.x; s.y *= m.y; s.z *= m.z; s.w *= m.w;
                int j = i >> 4, b0 = (i & 15) * 4;
                const float* ps = (const float*)&s;
#pragma unroll
                for (int q = 0; q < 4; q++) {
                    u16 hi, lo; bsplit(ps[q], hi, lo);
                    int p = bpk_idx(b0 + q, j);
                    g_xpk[p] = hi; g_xpk[p + 4] = lo;
                }
            }
        }
        gbarf(ep);

        // ---- P2: gate partials = w_hm @ x2 (296 ragged units over 30 rowtiles) ----
        for (int u = blockIdx.x; u < NU2; u += gridDim.x) {
            int ks = u / 30, rt = u - ks * 30;
            int nks = (rt < 26) ? 10 : 9;
            int kb0 = (ks * NKC) / nks, kb1 = ((ks + 1) * NKC) / nks;
            tc_warp(g_w2hi, g_w2lo, g_xpk, g_gpart[ks],
                    rt * 256 + wid * 16, kb0, kb1);
        }
        gbarf(ep);

        // ---- P3: gates + c/h update + hs + packed h scatter ----
        {
            __syncthreads();
            if (tid < Bsz) s_tok[tid] = xb[(size_t)tid * Lseq + t];
            __syncthreads();
            float* hs = g_hsT + (size_t)t * HB;
            for (int i = gid; i < HB / 4; i += gstride) {
                int hj = i >> 4, b0 = (i & 15) * 4;
                float4 gv[4];
#pragma unroll
                for (int gg = 0; gg < 4; gg++) {
                    int r = gg * KP_GATE + hj;
                    float4 a;
                    a.x = g_gxtok[s_tok[b0]][gg * Hdim + hj];
                    a.y = g_gxtok[s_tok[b0 + 1]][gg * Hdim + hj];
                    a.z = g_gxtok[s_tok[b0 + 2]][gg * Hdim + hj];
                    a.w = g_gxtok[s_tok[b0 + 3]][gg * Hdim + hj];
#pragma unroll
                    for (int ks = 0; ks < 10; ks++) {
                        float4 p = *(const float4*)(g_gpart[ks] + (size_t)r * 64 + b0);
                        a.x += p.x; a.y += p.y; a.z += p.z; a.w += p.w;
                    }
                    gv[gg] = a;
                }
                float4 c4 = ((const float4*)g_cT)[i];
                float4 h4;
                const float* pi = (const float*)&gv[0];
                const float* pf = (const float*)&gv[1];
                const float* pg = (const float*)&gv[2];
                const float* po = (const float*)&gv[3];
                float* pc = (float*)&c4;
                float* ph = (float*)&h4;
#pragma unroll
                for (int q = 0; q < 4; q++) {
                    float si = __fdividef(1.f, 1.f + __expf(-pi[q]));
                    float sf = __fdividef(1.f, 1.f + __expf(-pf[q]));
                    float so = __fdividef(1.f, 1.f + __expf(-po[q]));
                    float c = sf * pc[q] + si * tanhf(pg[q]);
                    pc[q] = c;
                    float h = so * tanhf(c);
                    ph[q] = h;
                    u16 hi, lo; bsplit(h, hi, lo);
                    int p = bpk_idx(b0 + q, hj);
                    g_hpk[p] = hi; g_hpk[p + 4] = lo;
                }
                ((float4*)g_cT)[i] = c4;
                ((float4*)hs)[i] = h4;
            }
        }
        gbarf(ep);
    }
    gbar_final();

    // ================= final projection =================
    for (int unit = blockIdx.x; unit < Lseq; unit += gridDim.x) {
        const float* X = g_hsT + (size_t)unit * HB;
        float acc[4];
#pragma unroll
        for (int q = 0; q < 4; q++) acc[q] = 0.f;
        int b = tid & 63, ng = tid >> 6;   // ng 0..7
        for (int kt = 0; kt < 60; kt++) {
            int k0 = kt * 32;
            __syncthreads();
#pragma unroll
            for (int u = 0; u < 4; u++) {
                int idx = u * TPB + tid;
                int k = k0 + (idx >> 6);
                s_proj[idx] = (k < Hdim) ? X[(size_t)k0 * 64 + idx] : 0.f;
            }
            __syncthreads();
            int klim = Hdim - k0; if (klim > 32) klim = 32;
            for (int kk = 0; kk < klim; kk++) {
                float xv = s_proj[kk * 64 + b];
#pragma unroll
                for (int q = 0; q < 4; q++) {
                    int n = ng + q * 8;
                    if (n < NOUT) acc[q] = fmaf(xv, w_lin[(size_t)n * Hdim + k0 + kk], acc[q]);
                }
            }
        }
#pragma unroll
        for (int q = 0; q < 4; q++) {
            int n = ng + q * 8;
            if (n < NOUT)
                out[((size_t)b * Lseq + unit) * NOUT + n] = acc[q] + b_lin[n];
        }
    }
}

// ---------------- launcher: ONE graph node ----------------
extern "C" void kernel_launch(void* const* d_in, const int* in_sizes, int n_in,
                              void* d_out, int out_size)
{
    (void)in_sizes; (void)n_in; (void)out_size;
    const int*   xb    = (const int*)  d_in[0];
    // d_in[1] = xb_lens (unused by the reference math)
    const float* h0    = (const float*)d_in[2];
    const float* c0    = (const float*)d_in[3];
    const float* etab  = (const float*)d_in[4];
    const float* w_mx  = (const float*)d_in[5];
    const float* w_mh  = (const float*)d_in[6];
    const float* w_ih  = (const float*)d_in[7];
    const float* w_hm  = (const float*)d_in[8];
    const float* bias  = (const float*)d_in[9];
    const float* w_lin = (const float*)d_in[10];
    const float* b_lin = (const float*)d_in[11];
    float* out = (float*)d_out;

    int sms = 0;
    if (cudaDeviceGetAttribute(&sms, cudaDevAttrMultiProcessorCount, 0) != cudaSuccess || sms <= 0)
        sms = 148;

    uni_kernel<<<sms, TPB>>>(xb, h0, c0, etab, w_mx, w_mh, w_ih, w_hm,
                             bias, w_lin, b_lin, out);
}

// round 12
// speedup vs baseline: 3.7843x; 1.0406x over previous
#include <cuda_runtime.h>
#include <cuda_bf16.h>
#include <math.h>
#include <stdint.h>

#define Bsz   64
#define Lseq  512
#define Edim  10
#define Hdim  1900
#define Grows 7600
#define NOUT  25
#define TPB   512
#define NTOK  30
#define KP_GATE 1920          // gate stride (rows) in W2 image space
#define NKC   119             // k16 chunks covering 1900
#define R1P   2048            // padded rows, W1 image space (8 rowtiles x 256)
#define R2P   7680            // padded rows, W2 image space (30 rowtiles x 256)
#define A1T   (R1P / 16)      // 128 m16 tiles
#define A2T   (R2P / 16)      // 480 m16 tiles
#define P1KS  18
#define NU1   (8 * P1KS)      // 144
#define NU2   296
#define HB    (Hdim * Bsz)    // 121600
#define NCMAX 14              // max k16 chunks per unit
#define SMEM_BYTES (NCMAX * 256 * 16)   // 57344 B: staged B fragments

typedef unsigned int u32;
typedef unsigned short u16;

// ---------------- scratch (__device__ globals; no allocations) ----------------
static __device__ float g_mxT[(size_t)Lseq * HB];
static __device__ float g_hsT[(size_t)Lseq * HB];
static __device__ float g_cT[HB];
static __device__ float g_m1part[P1KS][R1P * Bsz];            // P1 k-split partials [row][b]
static __device__ float g_gpart[10][R2P * Bsz];               // P2 k-split partials [row][b]
static __device__ float g_mxtok[NTOK][Hdim];
static __device__ float g_gxtok[NTOK][Grows];
// fragment-packed operand images (u16 bf16), layout [tile][kc][lane][8 u16]
static __device__ __align__(16) u16 g_w1hi[(size_t)A1T * NKC * 256];
static __device__ __align__(16) u16 g_w1lo[(size_t)A1T * NKC * 256];
static __device__ __align__(16) u16 g_w2hi[(size_t)A2T * NKC * 256];
static __device__ __align__(16) u16 g_w2lo[(size_t)A2T * NKC * 256];
static __device__ __align__(16) u16 g_hpk[8 * NKC * 256];     // h packed (hi+lo interleaved)
static __device__ __align__(16) u16 g_xpk[8 * NKC * 256];     // x2 packed
static __device__ volatile unsigned g_arrive;
static __device__ unsigned g_cnt;
static __device__ volatile unsigned g_gen;

// ---------------- helpers ----------------
__device__ __forceinline__ void bsplit(float v, u16& hi, u16& lo) {
    __nv_bfloat16 h = __float2bfloat16(v);
    hi = *reinterpret_cast<u16*>(&h);
    __nv_bfloat16 l = __float2bfloat16(v - __bfloat162float(h));
    lo = *reinterpret_cast<u16*>(&l);
}
__device__ __forceinline__ void mma_bf16(float d[4], const u32 a0, const u32 a1, const u32 a2, const u32 a3,
                                         const u32 b0, const u32 b1) {
    asm volatile(
        "mma.sync.aligned.m16n8k16.row.col.f32.bf16.bf16.f32 "
        "{%0,%1,%2,%3}, {%4,%5,%6,%7}, {%8,%9}, {%0,%1,%2,%3};"
        : "+f"(d[0]), "+f"(d[1]), "+f"(d[2]), "+f"(d[3])
        : "r"(a0), "r"(a1), "r"(a2), "r"(a3), "r"(b0), "r"(b1));
}
// packed u16 index for B-style images: element (b, k), hi part (+4 for lo)
__device__ __forceinline__ int bpk_idx(int b, int k) {
    return ((((b >> 3) * NKC + (k >> 4)) * 32 + 4 * (b & 7) + ((k & 7) >> 1)) << 3)
           + (((k >> 3) & 1) << 1) + (k & 1);
}

// ---------------- barriers ----------------
__device__ __forceinline__ void gbarf(unsigned& ep) {
    __syncthreads();
    ep += 1;
    if (threadIdx.x == 0) {
        unsigned tgt = ep * (unsigned)gridDim.x;
        __threadfence();
        atomicAdd((unsigned*)&g_arrive, 1u);
        while ((int)(g_arrive - tgt) < 0) __nanosleep(32);
        __threadfence();
    }
    __syncthreads();
}
__device__ __forceinline__ void gbar_final() {
    __syncthreads();
    if (threadIdx.x == 0) {
        unsigned gen = g_gen;
        __threadfence();
        if (atomicAdd(&g_cnt, 1u) == gridDim.x - 1) {
            g_cnt = 0;
            g_arrive = 0;
            __threadfence();
            g_gen = gen + 1;
        } else {
            while (g_gen == gen) __nanosleep(32);
        }
        __threadfence();
    }
    __syncthreads();
}

// ---------------- block unit: 256 rows x 64 b over k16 chunks [kb0,kb1) ----------------
// B k-range staged into smem cooperatively; A register double-buffered from global.
__device__ __forceinline__ void tc_unit(const u16* __restrict__ Whi, const u16* __restrict__ Wlo,
                                        const u16* __restrict__ Bpk, uint4* __restrict__ sB4,
                                        float* __restrict__ dst,
                                        int rowbase, int kb0, int kb1, int tid, int wid)
{
    const int nchunks = kb1 - kb0;

    // ---- stage B fragments for this k-range into smem (coalesced uint4) ----
    __syncthreads();    // previous unit's readers done before overwrite
    const uint4* Bp = (const uint4*)Bpk;
    for (int idx = tid; idx < nchunks * 256; idx += TPB) {
        int c = idx >> 8, r = idx & 255;
        int n = r >> 5, ln = r & 31;
        sB4[idx] = Bp[((size_t)n * NKC + kb0 + c) * 32 + ln];
    }
    __syncthreads();

    // ---- per-warp MMA: warp wid handles m16 tile rowbase/16 + wid ----
    const int lane = tid & 31;
    const int g = lane >> 2, t4 = lane & 3;
    const int mt = (rowbase >> 4) + wid;
    const uint4* Ah = (const uint4*)Whi;
    const uint4* Al = (const uint4*)Wlo;

    float d[8][4];
#pragma unroll
    for (int n = 0; n < 8; n++)
#pragma unroll
        for (int q = 0; q < 4; q++) d[n][q] = 0.f;

    const size_t abase = ((size_t)mt * NKC + kb0) * 32 + lane;
    uint4 ahc = Ah[abase];
    uint4 alc = Al[abase];

    for (int c = 0; c < nchunks; c++) {
        uint4 ahn, aln;
        if (c + 1 < nchunks) {              // prefetch next A chunk before MMAs
            ahn = Ah[abase + (size_t)(c + 1) * 32];
            aln = Al[abase + (size_t)(c + 1) * 32];
        }
        const uint4* bs = sB4 + c * 256 + lane;
#pragma unroll
        for (int n = 0; n < 8; n++) {
            uint4 bp = bs[n * 32];
            mma_bf16(d[n], ahc.x, ahc.y, ahc.z, ahc.w, bp.x, bp.y); // hi*hi
            mma_bf16(d[n], ahc.x, ahc.y, ahc.z, ahc.w, bp.z, bp.w); // hi*lo
            mma_bf16(d[n], alc.x, alc.y, alc.z, alc.w, bp.x, bp.y); // lo*hi
        }
        ahc = ahn; alc = aln;
    }

    // ---- writeback ----
    int r = mt * 16 + g;
#pragma unroll
    for (int n = 0; n < 8; n++) {
        *(float2*)(dst + (size_t)r * 64 + n * 8 + 2 * t4)       = make_float2(d[n][0], d[n][1]);
        *(float2*)(dst + (size_t)(r + 8) * 64 + n * 8 + 2 * t4) = make_float2(d[n][2], d[n][3]);
    }
}

// ---------------- persistent kernel ----------------
__global__ void __launch_bounds__(TPB, 1) uni_kernel(
    const int*   __restrict__ xb,
    const float* __restrict__ h0,    const float* __restrict__ c0,
    const float* __restrict__ etab,
    const float* __restrict__ w_mx,  const float* __restrict__ w_mh,
    const float* __restrict__ w_ih,  const float* __restrict__ w_hm,
    const float* __restrict__ bias,
    const float* __restrict__ w_lin, const float* __restrict__ b_lin,
    float* __restrict__ out)
{
    extern __shared__ __align__(16) char dsm[];
    uint4* sB4 = (uint4*)dsm;          // B fragment staging (57 KB)
    float* s_proj = (float*)dsm;       // overlay for final projection
    __shared__ int s_tok[Bsz];

    const int tid = threadIdx.x;
    const int wid = tid >> 5;          // 0..15
    const int gid = blockIdx.x * TPB + tid;
    const int gstride = gridDim.x * TPB;
    unsigned ep = 0;

    // ================= pre phase A =================
    for (int i = gid; i < NTOK * Hdim; i += gstride) {
        int v = i / Hdim, j = i - v * Hdim;
        float a = 0.f;
        if (v != 0)
#pragma unroll
            for (int e = 0; e < Edim; e++)
                a = fmaf(etab[(size_t)v * Edim + e], w_mx[(size_t)j * Edim + e], a);
        g_mxtok[v][j] = a;
    }
    for (int i = gid; i < NTOK * Grows; i += gstride) {
        int v = i / Grows, r = i - v * Grows;
        float a = bias[r];
        if (v != 0)
#pragma unroll
            for (int e = 0; e < Edim; e++)
                a = fmaf(etab[(size_t)v * Edim + e], w_ih[(size_t)r * Edim + e], a);
        g_gxtok[v][r] = a;
    }
    for (int i = gid; i < HB; i += gstride) {
        int j = i >> 6, b = i & 63;
        g_cT[i] = c0[(size_t)b * Hdim + j];
    }
    for (int i = gid; i < 8 * NKC * 256; i += gstride) { g_hpk[i] = 0; g_xpk[i] = 0; }
    gbarf(ep);
    for (int i = gid; i < HB; i += gstride) {
        int j = i >> 6, b = i & 63;
        u16 hi, lo; bsplit(h0[(size_t)b * Hdim + j], hi, lo);
        int p = bpk_idx(b, j);
        g_hpk[p] = hi; g_hpk[p + 4] = lo;
    }
    for (int i = gid; i < R2P * Bsz; i += gstride) g_gpart[9][i] = 0.f;
    // W1 fragment-packed image (w_mh)
    for (size_t i = gid; i < (size_t)A1T * NKC * 256; i += gstride) {
        int mt = (int)(i / (NKC * 256));
        int rem = (int)(i - (size_t)mt * (NKC * 256));
        int kc = rem >> 8, r2 = rem & 255;
        int lane = r2 >> 3, e = r2 & 7;
        int g = lane >> 2, t4 = lane & 3;
        int q = e >> 1, bit = e & 1;
        int row = mt * 16 + g + ((q & 1) ? 8 : 0);
        int col = kc * 16 + 2 * t4 + ((q & 2) ? 8 : 0) + bit;
        float v = (row < Hdim && col < Hdim) ? w_mh[(size_t)row * Hdim + col] : 0.f;
        u16 hi, lo; bsplit(v, hi, lo);
        g_w1hi[i] = hi; g_w1lo[i] = lo;
    }
    // W2 fragment-packed image (w_hm); image row = gate*1920 + hj
    for (size_t i = gid; i < (size_t)A2T * NKC * 256; i += gstride) {
        int mt = (int)(i / (NKC * 256));
        int rem = (int)(i - (size_t)mt * (NKC * 256));
        int kc = rem >> 8, r2 = rem & 255;
        int lane = r2 >> 3, e = r2 & 7;
        int g = lane >> 2, t4 = lane & 3;
        int q = e >> 1, bit = e & 1;
        int row = mt * 16 + g + ((q & 1) ? 8 : 0);
        int col = kc * 16 + 2 * t4 + ((q & 2) ? 8 : 0) + bit;
        int gate = row / KP_GATE, hj = row - gate * KP_GATE;
        float v = 0.f;
        if (hj < Hdim && col < Hdim)
            v = w_hm[((size_t)gate * Hdim + hj) * Hdim + col];
        u16 hi, lo; bsplit(v, hi, lo);
        g_w2hi[i] = hi; g_w2lo[i] = lo;
    }
    gbarf(ep);

    // ================= pre phase B: mxT =================
    for (int unit = blockIdx.x; unit < Lseq; unit += gridDim.x) {
        __syncthreads();
        if (tid < Bsz) s_tok[tid] = xb[(size_t)tid * Lseq + unit];
        __syncthreads();
        float* dst = g_mxT + (size_t)unit * HB;
        for (int i = tid; i < HB; i += TPB) {
            int j = i >> 6, b = i & 63;
            dst[i] = g_mxtok[s_tok[b]][j];
        }
    }
    gbarf(ep);

    // ================= recurrent loop =================
    for (int t = 0; t < Lseq; t++) {
        // ---- P1: mdot partials = w_mh @ h (144 units: 8 rowtiles x 18 ksplits) ----
        for (int u = blockIdx.x; u < NU1; u += gridDim.x) {
            int rt = u / P1KS, ks = u - rt * P1KS;
            int kb0 = (ks * NKC) / P1KS, kb1 = ((ks + 1) * NKC) / P1KS;
            tc_unit(g_w1hi, g_w1lo, g_hpk, sB4, g_m1part[ks],
                    rt * 256, kb0, kb1, tid, wid);
        }
        gbarf(ep);

        // ---- P1.5: reduce partials, x2 = mdot*mx, scatter into packed x image ----
        {
            const float4* mx4 = (const float4*)(g_mxT + (size_t)t * HB);
            for (int i = gid; i < HB / 4; i += gstride) {
                float4 s = ((const float4*)g_m1part[0])[i];
#pragma unroll
                for (int ks = 1; ks < P1KS; ks++) {
                    float4 p = ((const float4*)g_m1part[ks])[i];
                    s.x += p.x; s.y += p.y; s.z += p.z; s.w += p.w;
                }
                float4 m = mx4[i];
                s.x *= m.x; s.y *= m.y; s.z *= m.z; s.w *= m.w;
                int j = i >> 4, b0 = (i & 15) * 4;
                const float* ps = (const float*)&s;
#pragma unroll
                for (int q = 0; q < 4; q++) {
                    u16 hi, lo; bsplit(ps[q], hi, lo);
                    int p = bpk_idx(b0 + q, j);
                    g_xpk[p] = hi; g_xpk[p + 4] = lo;
                }
            }
        }
        gbarf(ep);

        // ---- P2: gate partials = w_hm @ x2 (296 ragged units over 30 rowtiles) ----
        for (int u = blockIdx.x; u < NU2; u += gridDim.x) {
            int ks = u / 30, rt = u - ks * 30;
            int nks = (rt < 26) ? 10 : 9;
            int kb0 = (ks * NKC) / nks, kb1 = ((ks + 1) * NKC) / nks;
            tc_unit(g_w2hi, g_w2lo, g_xpk, sB4, g_gpart[ks],
                    rt * 256, kb0, kb1, tid, wid);
        }
        gbarf(ep);

        // ---- P3: gates + c/h update + hs + packed h scatter ----
        {
            __syncthreads();
            if (tid < Bsz) s_tok[tid] = xb[(size_t)tid * Lseq + t];
            __syncthreads();
            float* hs = g_hsT + (size_t)t * HB;
            for (int i = gid; i < HB / 4; i += gstride) {
                int hj = i >> 4, b0 = (i & 15) * 4;
                float4 gv[4];
#pragma unroll
                for (int gg = 0; gg < 4; gg++) {
                    int r = gg * KP_GATE + hj;
                    float4 a;
                    a.x = g_gxtok[s_tok[b0]][gg * Hdim + hj];
                    a.y = g_gxtok[s_tok[b0 + 1]][gg * Hdim + hj];
                    a.z = g_gxtok[s_tok[b0 + 2]][gg * Hdim + hj];
                    a.w = g_gxtok[s_tok[b0 + 3]][gg * Hdim + hj];
#pragma unroll
                    for (int ks = 0; ks < 10; ks++) {
                        float4 p = *(const float4*)(g_gpart[ks] + (size_t)r * 64 + b0);
                        a.x += p.x; a.y += p.y; a.z += p.z; a.w += p.w;
                    }
                    gv[gg] = a;
                }
                float4 c4 = ((const float4*)g_cT)[i];
                float4 h4;
                const float* pi = (const float*)&gv[0];
                const float* pf = (const float*)&gv[1];
                const float* pg = (const float*)&gv[2];
                const float* po = (const float*)&gv[3];
                float* pc = (float*)&c4;
                float* ph = (float*)&h4;
#pragma unroll
                for (int q = 0; q < 4; q++) {
                    float si = __fdividef(1.f, 1.f + __expf(-pi[q]));
                    float sf = __fdividef(1.f, 1.f + __expf(-pf[q]));
                    float so = __fdividef(1.f, 1.f + __expf(-po[q]));
                    float c = sf * pc[q] + si * tanhf(pg[q]);
                    pc[q] = c;
                    float h = so * tanhf(c);
                    ph[q] = h;
                    u16 hi, lo; bsplit(h, hi, lo);
                    int p = bpk_idx(b0 + q, hj);
                    g_hpk[p] = hi; g_hpk[p + 4] = lo;
                }
                ((float4*)g_cT)[i] = c4;
                ((float4*)hs)[i] = h4;
            }
        }
        gbarf(ep);
    }
    gbar_final();

    // ================= final projection =================
    for (int unit = blockIdx.x; unit < Lseq; unit += gridDim.x) {
        const float* X = g_hsT + (size_t)unit * HB;
        float acc[4];
#pragma unroll
        for (int q = 0; q < 4; q++) acc[q] = 0.f;
        int b = tid & 63, ng = tid >> 6;   // ng 0..7
        for (int kt = 0; kt < 60; kt++) {
            int k0 = kt * 32;
            __syncthreads();
#pragma unroll
            for (int u = 0; u < 4; u++) {
                int idx = u * TPB + tid;
                int k = k0 + (idx >> 6);
                s_proj[idx] = (k < Hdim) ? X[(size_t)k0 * 64 + idx] : 0.f;
            }
            __syncthreads();
            int klim = Hdim - k0; if (klim > 32) klim = 32;
            for (int kk = 0; kk < klim; kk++) {
                float xv = s_proj[kk * 64 + b];
#pragma unroll
                for (int q = 0; q < 4; q++) {
                    int n = ng + q * 8;
                    if (n < NOUT) acc[q] = fmaf(xv, w_lin[(size_t)n * Hdim + k0 + kk], acc[q]);
                }
            }
        }
#pragma unroll
        for (int q = 0; q < 4; q++) {
            int n = ng + q * 8;
            if (n < NOUT)
                out[((size_t)b * Lseq + unit) * NOUT + n] = acc[q] + b_lin[n];
        }
    }
}

// ---------------- launcher: ONE graph node ----------------
extern "C" void kernel_launch(void* const* d_in, const int* in_sizes, int n_in,
                              void* d_out, int out_size)
{
    (void)in_sizes; (void)n_in; (void)out_size;
    const int*   xb    = (const int*)  d_in[0];
    // d_in[1] = xb_lens (unused by the reference math)
    const float* h0    = (const float*)d_in[2];
    const float* c0    = (const float*)d_in[3];
    const float* etab  = (const float*)d_in[4];
    const float* w_mx  = (const float*)d_in[5];
    const float* w_mh  = (const float*)d_in[6];
    const float* w_ih  = (const float*)d_in[7];
    const float* w_hm  = (const float*)d_in[8];
    const float* bias  = (const float*)d_in[9];
    const float* w_lin = (const float*)d_in[10];
    const float* b_lin = (const float*)d_in[11];
    float* out = (float*)d_out;

    static int smem_set = 0;
    if (!smem_set) {
        cudaFuncSetAttribute(uni_kernel, cudaFuncAttributeMaxDynamicSharedMemorySize, SMEM_BYTES);
        smem_set = 1;
    }

    int sms = 0;
    if (cudaDeviceGetAttribute(&sms, cudaDevAttrMultiProcessorCount, 0) != cudaSuccess || sms <= 0)
        sms = 148;

    uni_kernel<<<sms, TPB, SMEM_BYTES>>>(xb, h0, c0, etab, w_mx, w_mh, w_ih, w_hm,
                                         bias, w_lin, b_lin, out);
}